// round 7
// baseline (speedup 1.0000x reference)
#include <cuda_runtime.h>
#include <cuda_bf16.h>
#include <cuda_fp16.h>
#include <math.h>
#include <stdint.h>

// Problem constants
#define BATCH   2
#define S_LEN   2048
#define DMODEL  1024
#define NHEAD   16
#define HDIM    64
#define QKVD    (3*DMODEL)     // 3072
#define ROWS    (BATCH*S_LEN)  // 4096
#define BH      (BATCH*NHEAD)  // 32

// Scratch (device globals). All hi/lo pairs are fp16 stored as ushort.
__device__ float g_qkv[ROWS * QKVD];                       // qkv fp32 (pre-rope)
__device__ unsigned short g_xh[ROWS * DMODEL],   g_xl[ROWS * DMODEL];
__device__ unsigned short g_wqh[QKVD * DMODEL],  g_wql[QKVD * DMODEL];
__device__ unsigned short g_wph[DMODEL * DMODEL],g_wpl[DMODEL * DMODEL];
__device__ unsigned short g_ch[ROWS * DMODEL],   g_cl[ROWS * DMODEL];
__device__ unsigned short g_qhh[BH * S_LEN * HDIM], g_qll[BH * S_LEN * HDIM];
__device__ unsigned short g_khh[BH * S_LEN * HDIM], g_kll[BH * S_LEN * HDIM];
__device__ unsigned short g_vth[BH * HDIM * S_LEN], g_vtl[BH * HDIM * S_LEN];

// ---------------------------------------------------------------------------
// helpers
// ---------------------------------------------------------------------------
__device__ __forceinline__ uint32_t f2h2(float a, float b) {
    __half2 t = __floats2half2_rn(a, b);
    return *reinterpret_cast<uint32_t*>(&t);
}
__device__ __forceinline__ float2 h2f2(uint32_t r) {
    __half2 h = *reinterpret_cast<__half2*>(&r);
    return __half22float2(h);
}
__device__ __forceinline__ uint32_t sptr(const void* p) {
    return (uint32_t)__cvta_generic_to_shared(p);
}
__device__ __forceinline__ void cp16(void* dst, const void* src) {
    asm volatile("cp.async.cg.shared.global [%0], [%1], 16;\n"
                 :: "r"(sptr(dst)), "l"(src));
}
__device__ __forceinline__ void cp_commit() { asm volatile("cp.async.commit_group;\n"); }
__device__ __forceinline__ void cp_wait0()  { asm volatile("cp.async.wait_group 0;\n"); }
__device__ __forceinline__ void cp_wait1()  { asm volatile("cp.async.wait_group 1;\n"); }

__device__ __forceinline__ void ldsm4(uint32_t* r, const void* p) {
    asm volatile("ldmatrix.sync.aligned.m8n8.x4.shared.b16 {%0,%1,%2,%3}, [%4];\n"
                 : "=r"(r[0]), "=r"(r[1]), "=r"(r[2]), "=r"(r[3]) : "r"(sptr(p)));
}
// f16 inputs, f32 accumulate
__device__ __forceinline__ void mma_f32acc(float* c, const uint32_t* a, const uint32_t* b) {
    asm volatile(
        "mma.sync.aligned.m16n8k16.row.col.f32.f16.f16.f32 "
        "{%0,%1,%2,%3}, {%4,%5,%6,%7}, {%8,%9}, {%0,%1,%2,%3};\n"
        : "+f"(c[0]), "+f"(c[1]), "+f"(c[2]), "+f"(c[3])
        : "r"(a[0]), "r"(a[1]), "r"(a[2]), "r"(a[3]), "r"(b[0]), "r"(b[1]));
}
// f16 inputs, f16 accumulate (2-reg D: (c0,c1),(c2,c3) packed halves)
__device__ __forceinline__ void mma_f16acc(uint32_t* c, const uint32_t* a, const uint32_t* b) {
    asm volatile(
        "mma.sync.aligned.m16n8k16.row.col.f16.f16.f16.f16 "
        "{%0,%1}, {%2,%3,%4,%5}, {%6,%7}, {%0,%1};\n"
        : "+r"(c[0]), "+r"(c[1])
        : "r"(a[0]), "r"(a[1]), "r"(a[2]), "r"(a[3]), "r"(b[0]), "r"(b[1]));
}

// ---------------------------------------------------------------------------
// 1) LayerNorm fused with split-fp16 output
// ---------------------------------------------------------------------------
__global__ void __launch_bounds__(256) ln_split_kernel(
    const float* __restrict__ x, const float* __restrict__ gamma,
    const float* __restrict__ beta, unsigned short* __restrict__ yh,
    unsigned short* __restrict__ yl)
{
    __shared__ float red_s[8], red_ss[8];
    __shared__ float sh_mean, sh_inv;
    int row = blockIdx.x;
    int tid = threadIdx.x;
    const float4* xr = (const float4*)(x + (size_t)row * DMODEL);
    float4 v = xr[tid];
    float s  = v.x + v.y + v.z + v.w;
    float ss = v.x*v.x + v.y*v.y + v.z*v.z + v.w*v.w;
    #pragma unroll
    for (int off = 16; off > 0; off >>= 1) {
        s  += __shfl_down_sync(0xffffffffu, s,  off);
        ss += __shfl_down_sync(0xffffffffu, ss, off);
    }
    int wid = tid >> 5, lane = tid & 31;
    if (lane == 0) { red_s[wid] = s; red_ss[wid] = ss; }
    __syncthreads();
    if (tid == 0) {
        float S = 0.f, SS = 0.f;
        #pragma unroll
        for (int i = 0; i < 8; ++i) { S += red_s[i]; SS += red_ss[i]; }
        float mean = S * (1.f / DMODEL);
        float var  = SS * (1.f / DMODEL) - mean * mean;
        sh_mean = mean;
        sh_inv  = rsqrtf(var + 1e-5f);
    }
    __syncthreads();
    float mean = sh_mean, inv = sh_inv;
    float4 gv = ((const float4*)gamma)[tid];
    float4 bv = ((const float4*)beta)[tid];
    float o0 = (v.x - mean) * inv * gv.x + bv.x;
    float o1 = (v.y - mean) * inv * gv.y + bv.y;
    float o2 = (v.z - mean) * inv * gv.z + bv.z;
    float o3 = (v.w - mean) * inv * gv.w + bv.w;
    float h0 = __half2float(__float2half_rn(o0));
    float h1 = __half2float(__float2half_rn(o1));
    float h2 = __half2float(__float2half_rn(o2));
    float h3 = __half2float(__float2half_rn(o3));
    uint2 hv = make_uint2(f2h2(h0, h1), f2h2(h2, h3));
    uint2 lv = make_uint2(f2h2(o0 - h0, o1 - h1), f2h2(o2 - h2, o3 - h3));
    *(uint2*)(yh + (size_t)row * DMODEL + tid * 4) = hv;
    *(uint2*)(yl + (size_t)row * DMODEL + tid * 4) = lv;
}

// ---------------------------------------------------------------------------
// split fp32 -> (hi, lo) fp16, 4 elements/thread (weights)
// ---------------------------------------------------------------------------
__global__ void __launch_bounds__(256) split_f16_kernel(
    const float* __restrict__ x, unsigned short* __restrict__ hi,
    unsigned short* __restrict__ lo, int n4)
{
    int i = blockIdx.x * 256 + threadIdx.x;
    if (i >= n4) return;
    float4 v = ((const float4*)x)[i];
    float h0 = __half2float(__float2half_rn(v.x));
    float h1 = __half2float(__float2half_rn(v.y));
    float h2 = __half2float(__float2half_rn(v.z));
    float h3 = __half2float(__float2half_rn(v.w));
    uint2 hv = make_uint2(f2h2(h0, h1), f2h2(h2, h3));
    uint2 lv = make_uint2(f2h2(v.x - h0, v.y - h1), f2h2(v.z - h2, v.w - h3));
    *(uint2*)(hi + (size_t)i * 4) = hv;
    *(uint2*)(lo + (size_t)i * 4) = lv;
}

// ---------------------------------------------------------------------------
// 2) Smem-staged double-buffered split-fp16 MMA GEMM.
//    C = A@B^T + bias. Block 128x128, BK=32, 8 warps (2x4), warp 64x32.
//    hi*hi -> f32 accum; cross terms (hi*lo + lo*hi) -> shared f16 accum.
// ---------------------------------------------------------------------------
#define GPAD 40
#define GTILE (128 * GPAD)            // ushorts per tile
#define GSTAGE (4 * GTILE)            // Ah,Al,Bh,Bl
#define GEMM_SMEM (2 * GSTAGE * 2)    // bytes

__global__ void __launch_bounds__(256) mma_gemm_smem(
    const unsigned short* __restrict__ Ahg, const unsigned short* __restrict__ Alg,
    const unsigned short* __restrict__ Bhg, const unsigned short* __restrict__ Blg,
    const float* __restrict__ bias, float* __restrict__ C,
    int M, int N, int K)
{
    extern __shared__ unsigned short smg[];
    int t = threadIdx.x;
    int wid = t >> 5, lane = t & 31;
    int wm = wid >> 2, wn = wid & 3;       // 2 x 4 warps, warp tile 64x32
    int g = lane >> 2, q = lane & 3;
    int mb = blockIdx.y * 128, nb = blockIdx.x * 128;

    float acc[4][4][4];
    uint32_t cac[4][4][2];
    #pragma unroll
    for (int mt = 0; mt < 4; ++mt)
        #pragma unroll
        for (int nt = 0; nt < 4; ++nt) {
            #pragma unroll
            for (int e = 0; e < 4; ++e) acc[mt][nt][e] = 0.f;
            cac[mt][nt][0] = 0u; cac[mt][nt][1] = 0u;
        }

    const int NKB = K >> 5;

    auto load_stage = [&](int st, int k0) {
        unsigned short* base = smg + st * GSTAGE;
        #pragma unroll
        for (int i = 0; i < 2; ++i) {
            int ch = t + i * 256;          // 0..511
            int row = ch >> 2, c = ch & 3;
            int soff = row * GPAD + c * 8;
            size_t goffA = (size_t)(mb + row) * K + k0 + c * 8;
            size_t goffB = (size_t)(nb + row) * K + k0 + c * 8;
            cp16(base + soff,             Ahg + goffA);
            cp16(base + GTILE + soff,     Alg + goffA);
            cp16(base + 2 * GTILE + soff, Bhg + goffB);
            cp16(base + 3 * GTILE + soff, Blg + goffB);
        }
        cp_commit();
    };

    load_stage(0, 0);

    for (int kb = 0; kb < NKB; ++kb) {
        cp_wait0();
        __syncthreads();
        if (kb + 1 < NKB) load_stage((kb + 1) & 1, (kb + 1) << 5);

        unsigned short* base = smg + (kb & 1) * GSTAGE;
        unsigned short* sAh = base;
        unsigned short* sAl = base + GTILE;
        unsigned short* sBh = base + 2 * GTILE;
        unsigned short* sBl = base + 3 * GTILE;

        #pragma unroll
        for (int kk = 0; kk < 2; ++kk) {
            uint32_t ah[4][4], al[4][4];
            #pragma unroll
            for (int mt = 0; mt < 4; ++mt) {
                int r = wm * 64 + mt * 16 + (lane & 15);
                int c = kk * 16 + (lane >> 4) * 8;
                ldsm4(ah[mt], sAh + r * GPAD + c);
                ldsm4(al[mt], sAl + r * GPAD + c);
            }
            uint32_t bh2[4][2], bl2[4][2];
            #pragma unroll
            for (int p = 0; p < 2; ++p) {
                int r = wn * 32 + p * 16 + ((lane >> 4) & 1) * 8 + (lane & 7);
                int c = kk * 16 + ((lane >> 3) & 1) * 8;
                uint32_t tmp[4];
                ldsm4(tmp, sBh + r * GPAD + c);
                bh2[2*p][0] = tmp[0]; bh2[2*p][1] = tmp[1];
                bh2[2*p+1][0] = tmp[2]; bh2[2*p+1][1] = tmp[3];
                ldsm4(tmp, sBl + r * GPAD + c);
                bl2[2*p][0] = tmp[0]; bl2[2*p][1] = tmp[1];
                bl2[2*p+1][0] = tmp[2]; bl2[2*p+1][1] = tmp[3];
            }
            // hi*hi in f32 accum
            #pragma unroll
            for (int mt = 0; mt < 4; ++mt)
                #pragma unroll
                for (int nt = 0; nt < 4; ++nt)
                    mma_f32acc(acc[mt][nt], ah[mt], bh2[nt]);
            // cross terms in f16 accum (shared accumulator)
            #pragma unroll
            for (int mt = 0; mt < 4; ++mt)
                #pragma unroll
                for (int nt = 0; nt < 4; ++nt)
                    mma_f16acc(cac[mt][nt], ah[mt], bl2[nt]);
            #pragma unroll
            for (int mt = 0; mt < 4; ++mt)
                #pragma unroll
                for (int nt = 0; nt < 4; ++nt)
                    mma_f16acc(cac[mt][nt], al[mt], bh2[nt]);
        }
    }

    #pragma unroll
    for (int mt = 0; mt < 4; ++mt) {
        #pragma unroll
        for (int nt = 0; nt < 4; ++nt) {
            int r = mb + wm * 64 + mt * 16 + g;
            int c = nb + wn * 32 + nt * 8 + q * 2;
            float b0 = bias[c], b1 = bias[c + 1];
            float2 x0 = h2f2(cac[mt][nt][0]);
            float2 x1 = h2f2(cac[mt][nt][1]);
            float2 v0; v0.x = acc[mt][nt][0] + x0.x + b0; v0.y = acc[mt][nt][1] + x0.y + b1;
            float2 v1; v1.x = acc[mt][nt][2] + x1.x + b0; v1.y = acc[mt][nt][3] + x1.y + b1;
            *(float2*)(C + (size_t)r * N + c)       = v0;
            *(float2*)(C + (size_t)(r + 8) * N + c) = v1;
        }
    }
}

// ---------------------------------------------------------------------------
// 3) RoPE + head-major split-fp16 relayout for Q (pre-scaled) and K.
// ---------------------------------------------------------------------------
__global__ void __launch_bounds__(256) rope_convert_kernel(
    const float* __restrict__ qkv,
    unsigned short* __restrict__ Qh, unsigned short* __restrict__ Ql,
    unsigned short* __restrict__ Kh, unsigned short* __restrict__ Kl)
{
    int idx = blockIdx.x * 256 + threadIdx.x;   // B*S*H*32
    int i  = idx & 31;
    int h  = (idx >> 5) & 15;
    int sb = idx >> 9;
    int s  = sb & (S_LEN - 1);
    int b  = sb >> 11;
    const double C = 0.28782844202394213;       // ln(10000)/32
    double ang = (double)s * exp(-C * (double)i);
    double n   = rint(ang * 0.15915494309189535); // 1/(2*pi)
    float ar   = (float)(ang - n * 6.283185307179586);
    float c  = cosf(ar);
    float sn = sinf(ar);

    size_t base = (size_t)sb * QKVD + h * (3 * HDIM);
    float q1 = qkv[base + i],      q2 = qkv[base + 32 + i];
    float k1 = qkv[base + 64 + i], k2 = qkv[base + 96 + i];
    float qo1 = (q1 * c - q2 * sn) * 0.125f;
    float qo2 = (q2 * c + q1 * sn) * 0.125f;
    float ko1 = k1 * c - k2 * sn;
    float ko2 = k2 * c + k1 * sn;

    size_t dst = ((size_t)(b * NHEAD + h) * S_LEN + s) * HDIM;
    float hq1 = __half2float(__float2half_rn(qo1));
    float hq2 = __half2float(__float2half_rn(qo2));
    float hk1 = __half2float(__float2half_rn(ko1));
    float hk2 = __half2float(__float2half_rn(ko2));
    Qh[dst + i]      = __half_as_ushort(__float2half_rn(qo1));
    Qh[dst + 32 + i] = __half_as_ushort(__float2half_rn(qo2));
    Ql[dst + i]      = __half_as_ushort(__float2half_rn(qo1 - hq1));
    Ql[dst + 32 + i] = __half_as_ushort(__float2half_rn(qo2 - hq2));
    Kh[dst + i]      = __half_as_ushort(__float2half_rn(ko1));
    Kh[dst + 32 + i] = __half_as_ushort(__float2half_rn(ko2));
    Kl[dst + i]      = __half_as_ushort(__float2half_rn(ko1 - hk1));
    Kl[dst + 32 + i] = __half_as_ushort(__float2half_rn(ko2 - hk2));
}

// ---------------------------------------------------------------------------
// 3b) V transpose + split-fp16: Vt[bh][d][s] from qkv v-part.
// ---------------------------------------------------------------------------
__global__ void __launch_bounds__(256) v_transpose_kernel(
    const float* __restrict__ qkv,
    unsigned short* __restrict__ Vth, unsigned short* __restrict__ Vtl)
{
    __shared__ float tile[64][67];
    int st = blockIdx.x, bh = blockIdx.y;
    int b = bh >> 4, h = bh & 15;
    int t = threadIdx.x;
    #pragma unroll
    for (int it = 0; it < 4; ++it) {
        int id = t + it * 256;            // 0..1023
        int sl = id >> 4, f4 = id & 15;
        int sb = b * S_LEN + st * 64 + sl;
        float4 v = *(const float4*)(qkv + (size_t)sb * QKVD + h * 192 + 128 + f4 * 4);
        tile[sl][f4*4+0] = v.x; tile[sl][f4*4+1] = v.y;
        tile[sl][f4*4+2] = v.z; tile[sl][f4*4+3] = v.w;
    }
    __syncthreads();
    #pragma unroll
    for (int it = 0; it < 16; ++it) {
        int d  = it * 4 + (t >> 6);
        int sl = t & 63;
        float v = tile[sl][d];
        float hv = __half2float(__float2half_rn(v));
        size_t dst = ((size_t)bh * HDIM + d) * S_LEN + st * 64 + sl;
        Vth[dst] = __half_as_ushort(__float2half_rn(v));
        Vtl[dst] = __half_as_ushort(__float2half_rn(v - hv));
    }
}

// ---------------------------------------------------------------------------
// 4) Tensor-core flash attention, fp16 splits; hi*hi f32-accum, cross f16-accum.
// ---------------------------------------------------------------------------
#define APAD 72
#define AQT (128 * APAD)   // Q tile ushorts
#define AKT (64 * APAD)    // K/V tile ushorts
#define AST (4 * AKT)      // one K/V stage: Kh,Kl,Vh,Vl
#define ATT_SMEM ((2 * AQT + 2 * AST) * 2)

__global__ void __launch_bounds__(256) attn_mma_kernel(
    const unsigned short* __restrict__ Qh, const unsigned short* __restrict__ Ql,
    const unsigned short* __restrict__ Kh, const unsigned short* __restrict__ Kl,
    const unsigned short* __restrict__ Vth, const unsigned short* __restrict__ Vtl,
    unsigned short* __restrict__ Ch, unsigned short* __restrict__ Cl)
{
    extern __shared__ unsigned short sma[];
    unsigned short* sQh = sma;
    unsigned short* sQl = sma + AQT;
    unsigned short* sKV = sma + 2 * AQT;   // 2 stages of [Kh|Kl|Vh|Vl]

    int qt = blockIdx.x, bh = blockIdx.y;
    int b = bh >> 4, h = bh & 15;
    int t = threadIdx.x;
    int w = t >> 5, lane = t & 31;
    int g = lane >> 2, q = lane & 3;

    auto load_kv = [&](int st, int kt) {
        unsigned short* sg = sKV + st * AST;
        size_t kbase = ((size_t)bh * S_LEN + kt * 64) * HDIM;
        #pragma unroll
        for (int i = 0; i < 2; ++i) {
            int ch = t + i * 256;     // 0..511
            int row = ch >> 3, c = ch & 7;
            int soff = row * APAD + c * 8;
            cp16(sg + soff,           Kh + kbase + row * 64 + c * 8);
            cp16(sg + AKT + soff,     Kl + kbase + row * 64 + c * 8);
            size_t vsrc = ((size_t)bh * HDIM + row) * S_LEN + kt * 64 + c * 8;
            cp16(sg + 2 * AKT + soff, Vth + vsrc);
            cp16(sg + 3 * AKT + soff, Vtl + vsrc);
        }
        cp_commit();
    };

    // prologue: stage Q, prefetch kv tile 0
    size_t qbase = ((size_t)bh * S_LEN + qt * 128) * HDIM;
    #pragma unroll
    for (int i = 0; i < 4; ++i) {
        int ch = t + i * 256;             // 0..1023
        int row = ch >> 3, c = ch & 7;
        cp16(sQh + row * APAD + c * 8, Qh + qbase + row * 64 + c * 8);
        cp16(sQl + row * APAD + c * 8, Ql + qbase + row * 64 + c * 8);
    }
    cp_commit();
    load_kv(0, 0);
    cp_wait1();
    __syncthreads();

    uint32_t qfh[4][4], qfl[4][4];
    #pragma unroll
    for (int kk = 0; kk < 4; ++kk) {
        int r = w * 16 + (lane & 15);
        int c = kk * 16 + (lane >> 4) * 8;
        ldsm4(qfh[kk], sQh + r * APAD + c);
        ldsm4(qfl[kk], sQl + r * APAD + c);
    }

    float o[8][4];
    #pragma unroll
    for (int nt = 0; nt < 8; ++nt)
        #pragma unroll
        for (int e = 0; e < 4; ++e) o[nt][e] = 0.f;
    float mA = -1e30f, mB = -1e30f, lA = 0.f, lB = 0.f;

    int qrA = qt * 128 + w * 16 + g;
    int qmax = qt * 128 + w * 16 + 15;
    int nk = 2 * qt + 2;

    for (int kt = 0; kt < nk; ++kt) {
        cp_wait0();
        __syncthreads();
        if (kt + 1 < nk) load_kv((kt + 1) & 1, kt + 1);

        if (kt * 64 <= qmax) {
            unsigned short* sg  = sKV + (kt & 1) * AST;
            unsigned short* sKh_ = sg;
            unsigned short* sKl_ = sg + AKT;
            unsigned short* sVh_ = sg + 2 * AKT;
            unsigned short* sVl_ = sg + 3 * AKT;

            float s_acc[8][4];
            uint32_t sc[8][2];
            #pragma unroll
            for (int nt = 0; nt < 8; ++nt) {
                #pragma unroll
                for (int e = 0; e < 4; ++e) s_acc[nt][e] = 0.f;
                sc[nt][0] = 0u; sc[nt][1] = 0u;
            }

            #pragma unroll
            for (int kk = 0; kk < 4; ++kk) {
                uint32_t bh2[8][2], bl2[8][2];
                #pragma unroll
                for (int p = 0; p < 4; ++p) {
                    int r = p * 16 + ((lane >> 4) & 1) * 8 + (lane & 7);
                    int c = kk * 16 + ((lane >> 3) & 1) * 8;
                    uint32_t tmp[4];
                    ldsm4(tmp, sKh_ + r * APAD + c);
                    bh2[2*p][0] = tmp[0]; bh2[2*p][1] = tmp[1];
                    bh2[2*p+1][0] = tmp[2]; bh2[2*p+1][1] = tmp[3];
                    ldsm4(tmp, sKl_ + r * APAD + c);
                    bl2[2*p][0] = tmp[0]; bl2[2*p][1] = tmp[1];
                    bl2[2*p+1][0] = tmp[2]; bl2[2*p+1][1] = tmp[3];
                }
                #pragma unroll
                for (int nt = 0; nt < 8; ++nt)
                    mma_f32acc(s_acc[nt], qfh[kk], bh2[nt]);
                #pragma unroll
                for (int nt = 0; nt < 8; ++nt)
                    mma_f16acc(sc[nt], qfh[kk], bl2[nt]);
                #pragma unroll
                for (int nt = 0; nt < 8; ++nt)
                    mma_f16acc(sc[nt], qfl[kk], bh2[nt]);
            }
            // drain f16 cross into f32 logits
            #pragma unroll
            for (int nt = 0; nt < 8; ++nt) {
                float2 x0 = h2f2(sc[nt][0]);
                float2 x1 = h2f2(sc[nt][1]);
                s_acc[nt][0] += x0.x; s_acc[nt][1] += x0.y;
                s_acc[nt][2] += x1.x; s_acc[nt][3] += x1.y;
            }

            int kb0 = kt * 64;
            if (kb0 + 63 > qrA) {
                #pragma unroll
                for (int nt = 0; nt < 8; ++nt) {
                    int colb = kb0 + nt * 8 + 2 * q;
                    if (colb     > qrA)     s_acc[nt][0] = -1e30f;
                    if (colb + 1 > qrA)     s_acc[nt][1] = -1e30f;
                    if (colb     > qrA + 8) s_acc[nt][2] = -1e30f;
                    if (colb + 1 > qrA + 8) s_acc[nt][3] = -1e30f;
                }
            }

            float mxA = -1e30f, mxB = -1e30f;
            #pragma unroll
            for (int nt = 0; nt < 8; ++nt) {
                mxA = fmaxf(mxA, fmaxf(s_acc[nt][0], s_acc[nt][1]));
                mxB = fmaxf(mxB, fmaxf(s_acc[nt][2], s_acc[nt][3]));
            }
            mxA = fmaxf(mxA, __shfl_xor_sync(0xffffffffu, mxA, 1));
            mxA = fmaxf(mxA, __shfl_xor_sync(0xffffffffu, mxA, 2));
            mxB = fmaxf(mxB, __shfl_xor_sync(0xffffffffu, mxB, 1));
            mxB = fmaxf(mxB, __shfl_xor_sync(0xffffffffu, mxB, 2));
            float mnA = fmaxf(mA, mxA), mnB = fmaxf(mB, mxB);
            float corrA = __expf(mA - mnA), corrB = __expf(mB - mnB);
            float psA = 0.f, psB = 0.f;
            #pragma unroll
            for (int nt = 0; nt < 8; ++nt) {
                s_acc[nt][0] = __expf(s_acc[nt][0] - mnA); psA += s_acc[nt][0];
                s_acc[nt][1] = __expf(s_acc[nt][1] - mnA); psA += s_acc[nt][1];
                s_acc[nt][2] = __expf(s_acc[nt][2] - mnB); psB += s_acc[nt][2];
                s_acc[nt][3] = __expf(s_acc[nt][3] - mnB); psB += s_acc[nt][3];
            }
            psA += __shfl_xor_sync(0xffffffffu, psA, 1);
            psA += __shfl_xor_sync(0xffffffffu, psA, 2);
            psB += __shfl_xor_sync(0xffffffffu, psB, 1);
            psB += __shfl_xor_sync(0xffffffffu, psB, 2);
            lA = lA * corrA + psA;  mA = mnA;
            lB = lB * corrB + psB;  mB = mnB;
            #pragma unroll
            for (int nt = 0; nt < 8; ++nt) {
                o[nt][0] *= corrA; o[nt][1] *= corrA;
                o[nt][2] *= corrB; o[nt][3] *= corrB;
            }

            uint32_t oc[8][2];
            #pragma unroll
            for (int nt = 0; nt < 8; ++nt) { oc[nt][0] = 0u; oc[nt][1] = 0u; }

            #pragma unroll
            for (int kk = 0; kk < 4; ++kk) {
                int n0 = 2 * kk, n1 = 2 * kk + 1;
                uint32_t ph[4], pl[4];
                ph[0] = f2h2(s_acc[n0][0], s_acc[n0][1]);
                ph[1] = f2h2(s_acc[n0][2], s_acc[n0][3]);
                ph[2] = f2h2(s_acc[n1][0], s_acc[n1][1]);
                ph[3] = f2h2(s_acc[n1][2], s_acc[n1][3]);
                {
                    float2 h0 = h2f2(ph[0]); float2 h1 = h2f2(ph[1]);
                    float2 h2_ = h2f2(ph[2]); float2 h3 = h2f2(ph[3]);
                    pl[0] = f2h2(s_acc[n0][0] - h0.x, s_acc[n0][1] - h0.y);
                    pl[1] = f2h2(s_acc[n0][2] - h1.x, s_acc[n0][3] - h1.y);
                    pl[2] = f2h2(s_acc[n1][0] - h2_.x, s_acc[n1][1] - h2_.y);
                    pl[3] = f2h2(s_acc[n1][2] - h3.x, s_acc[n1][3] - h3.y);
                }
                uint32_t vh2[8][2], vl2[8][2];
                #pragma unroll
                for (int p = 0; p < 4; ++p) {
                    int r = p * 16 + ((lane >> 4) & 1) * 8 + (lane & 7);
                    int c = kk * 16 + ((lane >> 3) & 1) * 8;
                    uint32_t tmp[4];
                    ldsm4(tmp, sVh_ + r * APAD + c);
                    vh2[2*p][0] = tmp[0]; vh2[2*p][1] = tmp[1];
                    vh2[2*p+1][0] = tmp[2]; vh2[2*p+1][1] = tmp[3];
                    ldsm4(tmp, sVl_ + r * APAD + c);
                    vl2[2*p][0] = tmp[0]; vl2[2*p][1] = tmp[1];
                    vl2[2*p+1][0] = tmp[2]; vl2[2*p+1][1] = tmp[3];
                }
                #pragma unroll
                for (int nt = 0; nt < 8; ++nt)
                    mma_f32acc(o[nt], ph, vh2[nt]);
                #pragma unroll
                for (int nt = 0; nt < 8; ++nt)
                    mma_f16acc(oc[nt], ph, vl2[nt]);
                #pragma unroll
                for (int nt = 0; nt < 8; ++nt)
                    mma_f16acc(oc[nt], pl, vh2[nt]);
            }
            // drain PV cross terms (unscaled: they belong to this tile)
            #pragma unroll
            for (int nt = 0; nt < 8; ++nt) {
                float2 x0 = h2f2(oc[nt][0]);
                float2 x1 = h2f2(oc[nt][1]);
                o[nt][0] += x0.x; o[nt][1] += x0.y;
                o[nt][2] += x1.x; o[nt][3] += x1.y;
            }
        }
    }

    float invA = 1.f / lA, invB = 1.f / lB;
    int rowA = qt * 128 + w * 16 + g;
    size_t baseA = ((size_t)(b * S_LEN + rowA)) * DMODEL + h * HDIM;
    size_t baseB = baseA + (size_t)8 * DMODEL;
    #pragma unroll
    for (int nt = 0; nt < 8; ++nt) {
        int c = nt * 8 + 2 * q;
        float a0 = o[nt][0] * invA, a1 = o[nt][1] * invA;
        float b0 = o[nt][2] * invB, b1 = o[nt][3] * invB;
        float ha0 = __half2float(__float2half_rn(a0));
        float ha1 = __half2float(__float2half_rn(a1));
        float hb0 = __half2float(__float2half_rn(b0));
        float hb1 = __half2float(__float2half_rn(b1));
        *(uint32_t*)(Ch + baseA + c) = f2h2(ha0, ha1);
        *(uint32_t*)(Cl + baseA + c) = f2h2(a0 - ha0, a1 - ha1);
        *(uint32_t*)(Ch + baseB + c) = f2h2(hb0, hb1);
        *(uint32_t*)(Cl + baseB + c) = f2h2(b0 - hb0, b1 - hb1);
    }
}

// ---------------------------------------------------------------------------
// Launcher
// ---------------------------------------------------------------------------
extern "C" void kernel_launch(void* const* d_in, const int* in_sizes, int n_in,
                              void* d_out, int out_size)
{
    const float* hs     = (const float*)d_in[0];
    const float* gamma  = (const float*)d_in[1];
    const float* beta   = (const float*)d_in[2];
    const float* qkv_w  = (const float*)d_in[3];
    const float* qkv_b  = (const float*)d_in[4];
    const float* proj_w = (const float*)d_in[5];
    const float* proj_b = (const float*)d_in[6];
    float* out = (float*)d_out;

    void *pqkv, *pxh, *pxl, *pwqh, *pwql, *pwph, *pwpl, *pch, *pcl;
    void *pqh, *pql, *pkh, *pkl, *pvh, *pvl;
    cudaGetSymbolAddress(&pqkv, g_qkv);
    cudaGetSymbolAddress(&pxh,  g_xh);  cudaGetSymbolAddress(&pxl,  g_xl);
    cudaGetSymbolAddress(&pwqh, g_wqh); cudaGetSymbolAddress(&pwql, g_wql);
    cudaGetSymbolAddress(&pwph, g_wph); cudaGetSymbolAddress(&pwpl, g_wpl);
    cudaGetSymbolAddress(&pch,  g_ch);  cudaGetSymbolAddress(&pcl,  g_cl);
    cudaGetSymbolAddress(&pqh,  g_qhh); cudaGetSymbolAddress(&pql,  g_qll);
    cudaGetSymbolAddress(&pkh,  g_khh); cudaGetSymbolAddress(&pkl,  g_kll);
    cudaGetSymbolAddress(&pvh,  g_vth); cudaGetSymbolAddress(&pvl,  g_vtl);

    cudaFuncSetAttribute(mma_gemm_smem,
        cudaFuncAttributeMaxDynamicSharedMemorySize, GEMM_SMEM);
    cudaFuncSetAttribute(attn_mma_kernel,
        cudaFuncAttributeMaxDynamicSharedMemorySize, ATT_SMEM);

    // 1) LayerNorm + fp16 split
    ln_split_kernel<<<ROWS, 256>>>(hs, gamma, beta,
        (unsigned short*)pxh, (unsigned short*)pxl);

    // weight splits (fp16)
    split_f16_kernel<<<(QKVD*DMODEL/4)/256, 256>>>(qkv_w,
        (unsigned short*)pwqh, (unsigned short*)pwql, QKVD*DMODEL/4);
    split_f16_kernel<<<(DMODEL*DMODEL/4)/256, 256>>>(proj_w,
        (unsigned short*)pwph, (unsigned short*)pwpl, DMODEL*DMODEL/4);

    // 2) QKV GEMM
    mma_gemm_smem<<<dim3(QKVD/128, ROWS/128), 256, GEMM_SMEM>>>(
        (unsigned short*)pxh, (unsigned short*)pxl,
        (unsigned short*)pwqh, (unsigned short*)pwql,
        qkv_b, (float*)pqkv, ROWS, QKVD, DMODEL);

    // 3) RoPE + relayout, V transpose (fp16)
    rope_convert_kernel<<<(BATCH*S_LEN*NHEAD*32)/256, 256>>>((float*)pqkv,
        (unsigned short*)pqh, (unsigned short*)pql,
        (unsigned short*)pkh, (unsigned short*)pkl);
    v_transpose_kernel<<<dim3(S_LEN/64, BH), 256>>>((float*)pqkv,
        (unsigned short*)pvh, (unsigned short*)pvl);

    // 4) Attention (writes fp16-split ctx)
    attn_mma_kernel<<<dim3(S_LEN/128, BH), 256, ATT_SMEM>>>(
        (unsigned short*)pqh, (unsigned short*)pql,
        (unsigned short*)pkh, (unsigned short*)pkl,
        (unsigned short*)pvh, (unsigned short*)pvl,
        (unsigned short*)pch, (unsigned short*)pcl);

    // 5) Output projection
    mma_gemm_smem<<<dim3(DMODEL/128, ROWS/128), 256, GEMM_SMEM>>>(
        (unsigned short*)pch, (unsigned short*)pcl,
        (unsigned short*)pwph, (unsigned short*)pwpl,
        proj_b, out, ROWS, DMODEL, DMODEL);
}

// round 8
// speedup vs baseline: 1.4064x; 1.4064x over previous
#include <cuda_runtime.h>
#include <cuda_fp16.h>
#include <math.h>
#include <stdint.h>

// Problem constants
#define BATCH   2
#define S_LEN   2048
#define DMODEL  1024
#define NHEAD   16
#define HDIM    64
#define QKVD    (3*DMODEL)     // 3072
#define ROWS    (BATCH*S_LEN)  // 4096
#define BH      (BATCH*NHEAD)  // 32

// Scratch (device globals). hi/lo fp16 stored as ushort.
__device__ float g_qkv[ROWS * QKVD];                       // qkv fp32 (pre-rope)
__device__ unsigned short g_xh[ROWS * DMODEL],   g_xl[ROWS * DMODEL];
__device__ unsigned short g_wqh[QKVD * DMODEL];            // weight hi only
__device__ unsigned short g_wph[DMODEL * DMODEL];
__device__ unsigned short g_ch[ROWS * DMODEL],   g_cl[ROWS * DMODEL];
__device__ unsigned short g_qhh[BH * S_LEN * HDIM], g_qll[BH * S_LEN * HDIM];
__device__ unsigned short g_khh[BH * S_LEN * HDIM];        // K hi only
__device__ unsigned short g_vth[BH * HDIM * S_LEN];        // V^T hi only

// ---------------------------------------------------------------------------
// helpers
// ---------------------------------------------------------------------------
__device__ __forceinline__ uint32_t f2h2(float a, float b) {
    __half2 t = __floats2half2_rn(a, b);
    return *reinterpret_cast<uint32_t*>(&t);
}
__device__ __forceinline__ uint32_t sptr(const void* p) {
    return (uint32_t)__cvta_generic_to_shared(p);
}
__device__ __forceinline__ void cp16(void* dst, const void* src) {
    asm volatile("cp.async.cg.shared.global [%0], [%1], 16;\n"
                 :: "r"(sptr(dst)), "l"(src));
}
__device__ __forceinline__ void cp_commit() { asm volatile("cp.async.commit_group;\n"); }
__device__ __forceinline__ void cp_wait0()  { asm volatile("cp.async.wait_group 0;\n"); }
__device__ __forceinline__ void cp_wait1()  { asm volatile("cp.async.wait_group 1;\n"); }

__device__ __forceinline__ void ldsm4(uint32_t* r, const void* p) {
    asm volatile("ldmatrix.sync.aligned.m8n8.x4.shared.b16 {%0,%1,%2,%3}, [%4];\n"
                 : "=r"(r[0]), "=r"(r[1]), "=r"(r[2]), "=r"(r[3]) : "r"(sptr(p)));
}
// f16 inputs, f32 accumulate
__device__ __forceinline__ void mma_f16(float* c, const uint32_t* a, const uint32_t* b) {
    asm volatile(
        "mma.sync.aligned.m16n8k16.row.col.f32.f16.f16.f32 "
        "{%0,%1,%2,%3}, {%4,%5,%6,%7}, {%8,%9}, {%0,%1,%2,%3};\n"
        : "+f"(c[0]), "+f"(c[1]), "+f"(c[2]), "+f"(c[3])
        : "r"(a[0]), "r"(a[1]), "r"(a[2]), "r"(a[3]), "r"(b[0]), "r"(b[1]));
}

// ---------------------------------------------------------------------------
// 1) LayerNorm fused with split-fp16 output (hi + lo)
// ---------------------------------------------------------------------------
__global__ void __launch_bounds__(256) ln_split_kernel(
    const float* __restrict__ x, const float* __restrict__ gamma,
    const float* __restrict__ beta, unsigned short* __restrict__ yh,
    unsigned short* __restrict__ yl)
{
    __shared__ float red_s[8], red_ss[8];
    __shared__ float sh_mean, sh_inv;
    int row = blockIdx.x;
    int tid = threadIdx.x;
    const float4* xr = (const float4*)(x + (size_t)row * DMODEL);
    float4 v = xr[tid];
    float s  = v.x + v.y + v.z + v.w;
    float ss = v.x*v.x + v.y*v.y + v.z*v.z + v.w*v.w;
    #pragma unroll
    for (int off = 16; off > 0; off >>= 1) {
        s  += __shfl_down_sync(0xffffffffu, s,  off);
        ss += __shfl_down_sync(0xffffffffu, ss, off);
    }
    int wid = tid >> 5, lane = tid & 31;
    if (lane == 0) { red_s[wid] = s; red_ss[wid] = ss; }
    __syncthreads();
    if (tid == 0) {
        float S = 0.f, SS = 0.f;
        #pragma unroll
        for (int i = 0; i < 8; ++i) { S += red_s[i]; SS += red_ss[i]; }
        float mean = S * (1.f / DMODEL);
        float var  = SS * (1.f / DMODEL) - mean * mean;
        sh_mean = mean;
        sh_inv  = rsqrtf(var + 1e-5f);
    }
    __syncthreads();
    float mean = sh_mean, inv = sh_inv;
    float4 gv = ((const float4*)gamma)[tid];
    float4 bv = ((const float4*)beta)[tid];
    float o0 = (v.x - mean) * inv * gv.x + bv.x;
    float o1 = (v.y - mean) * inv * gv.y + bv.y;
    float o2 = (v.z - mean) * inv * gv.z + bv.z;
    float o3 = (v.w - mean) * inv * gv.w + bv.w;
    float h0 = __half2float(__float2half_rn(o0));
    float h1 = __half2float(__float2half_rn(o1));
    float h2 = __half2float(__float2half_rn(o2));
    float h3 = __half2float(__float2half_rn(o3));
    uint2 hv = make_uint2(f2h2(h0, h1), f2h2(h2, h3));
    uint2 lv = make_uint2(f2h2(o0 - h0, o1 - h1), f2h2(o2 - h2, o3 - h3));
    *(uint2*)(yh + (size_t)row * DMODEL + tid * 4) = hv;
    *(uint2*)(yl + (size_t)row * DMODEL + tid * 4) = lv;
}

// ---------------------------------------------------------------------------
// weights: fp32 -> fp16 hi only, 4 elements/thread
// ---------------------------------------------------------------------------
__global__ void __launch_bounds__(256) w_f16_kernel(
    const float* __restrict__ x, unsigned short* __restrict__ hi, int n4)
{
    int i = blockIdx.x * 256 + threadIdx.x;
    if (i >= n4) return;
    float4 v = ((const float4*)x)[i];
    uint2 hv = make_uint2(f2h2(v.x, v.y), f2h2(v.z, v.w));
    *(uint2*)(hi + (size_t)i * 4) = hv;
}

// ---------------------------------------------------------------------------
// 2) Smem-staged double-buffered 2-term split GEMM.
//    C = A@B^T + bias: Ah*Bh + Al*Bh (corrects activation rounding).
//    Block 128x128, BK=32, 4 warps (2x2), warp tile 64x64.
// ---------------------------------------------------------------------------
#define GPAD 40
#define GTILE (128 * GPAD)            // ushorts per tile
#define GSTAGE (3 * GTILE)            // Ah,Al,Bh
#define GEMM_SMEM (2 * GSTAGE * 2)    // bytes = 61440

__global__ void __launch_bounds__(128) mma_gemm_smem(
    const unsigned short* __restrict__ Ahg, const unsigned short* __restrict__ Alg,
    const unsigned short* __restrict__ Bhg,
    const float* __restrict__ bias, float* __restrict__ C,
    int M, int N, int K)
{
    extern __shared__ unsigned short smg[];
    int t = threadIdx.x;
    int wid = t >> 5, lane = t & 31;
    int wm = wid >> 1, wn = wid & 1;
    int g = lane >> 2, q = lane & 3;
    int mb = blockIdx.y * 128, nb = blockIdx.x * 128;

    float acc[4][8][4];
    #pragma unroll
    for (int mt = 0; mt < 4; ++mt)
        #pragma unroll
        for (int nt = 0; nt < 8; ++nt)
            #pragma unroll
            for (int e = 0; e < 4; ++e) acc[mt][nt][e] = 0.f;

    const int NKB = K >> 5;

    auto load_stage = [&](int st, int k0) {
        unsigned short* base = smg + st * GSTAGE;
        #pragma unroll
        for (int i = 0; i < 4; ++i) {
            int ch = t + i * 128;          // 0..511
            int row = ch >> 2, c = ch & 3;
            int soff = row * GPAD + c * 8;
            size_t goffA = (size_t)(mb + row) * K + k0 + c * 8;
            size_t goffB = (size_t)(nb + row) * K + k0 + c * 8;
            cp16(base + soff,             Ahg + goffA);
            cp16(base + GTILE + soff,     Alg + goffA);
            cp16(base + 2 * GTILE + soff, Bhg + goffB);
        }
        cp_commit();
    };

    load_stage(0, 0);

    for (int kb = 0; kb < NKB; ++kb) {
        cp_wait0();
        __syncthreads();
        if (kb + 1 < NKB) load_stage((kb + 1) & 1, (kb + 1) << 5);

        unsigned short* base = smg + (kb & 1) * GSTAGE;
        unsigned short* sAh = base;
        unsigned short* sAl = base + GTILE;
        unsigned short* sBh = base + 2 * GTILE;

        #pragma unroll
        for (int kk = 0; kk < 2; ++kk) {
            uint32_t ah[4][4], al[4][4];
            #pragma unroll
            for (int mt = 0; mt < 4; ++mt) {
                int r = wm * 64 + mt * 16 + (lane & 15);
                int c = kk * 16 + (lane >> 4) * 8;
                ldsm4(ah[mt], sAh + r * GPAD + c);
                ldsm4(al[mt], sAl + r * GPAD + c);
            }
            uint32_t bh2[8][2];
            #pragma unroll
            for (int p = 0; p < 4; ++p) {
                int r = wn * 64 + p * 16 + ((lane >> 4) & 1) * 8 + (lane & 7);
                int c = kk * 16 + ((lane >> 3) & 1) * 8;
                uint32_t tmp[4];
                ldsm4(tmp, sBh + r * GPAD + c);
                bh2[2*p][0] = tmp[0]; bh2[2*p][1] = tmp[1];
                bh2[2*p+1][0] = tmp[2]; bh2[2*p+1][1] = tmp[3];
            }
            #pragma unroll
            for (int mt = 0; mt < 4; ++mt)
                #pragma unroll
                for (int nt = 0; nt < 8; ++nt)
                    mma_f16(acc[mt][nt], ah[mt], bh2[nt]);
            #pragma unroll
            for (int mt = 0; mt < 4; ++mt)
                #pragma unroll
                for (int nt = 0; nt < 8; ++nt)
                    mma_f16(acc[mt][nt], al[mt], bh2[nt]);
        }
    }

    #pragma unroll
    for (int mt = 0; mt < 4; ++mt) {
        #pragma unroll
        for (int nt = 0; nt < 8; ++nt) {
            int r = mb + wm * 64 + mt * 16 + g;
            int c = nb + wn * 64 + nt * 8 + q * 2;
            float b0 = bias[c], b1 = bias[c + 1];
            float2 v0; v0.x = acc[mt][nt][0] + b0; v0.y = acc[mt][nt][1] + b1;
            float2 v1; v1.x = acc[mt][nt][2] + b0; v1.y = acc[mt][nt][3] + b1;
            *(float2*)(C + (size_t)r * N + c)       = v0;
            *(float2*)(C + (size_t)(r + 8) * N + c) = v1;
        }
    }
}

// ---------------------------------------------------------------------------
// 3) RoPE + head-major relayout: Q (pre-scaled) hi+lo, K hi only.
// ---------------------------------------------------------------------------
__global__ void __launch_bounds__(256) rope_convert_kernel(
    const float* __restrict__ qkv,
    unsigned short* __restrict__ Qh, unsigned short* __restrict__ Ql,
    unsigned short* __restrict__ Kh)
{
    int idx = blockIdx.x * 256 + threadIdx.x;   // B*S*H*32
    int i  = idx & 31;
    int h  = (idx >> 5) & 15;
    int sb = idx >> 9;
    int s  = sb & (S_LEN - 1);
    int b  = sb >> 11;
    const double C = 0.28782844202394213;       // ln(10000)/32
    double ang = (double)s * exp(-C * (double)i);
    double n   = rint(ang * 0.15915494309189535); // 1/(2*pi)
    float ar   = (float)(ang - n * 6.283185307179586);
    float c  = cosf(ar);
    float sn = sinf(ar);

    size_t base = (size_t)sb * QKVD + h * (3 * HDIM);
    float q1 = qkv[base + i],      q2 = qkv[base + 32 + i];
    float k1 = qkv[base + 64 + i], k2 = qkv[base + 96 + i];
    float qo1 = (q1 * c - q2 * sn) * 0.125f;
    float qo2 = (q2 * c + q1 * sn) * 0.125f;
    float ko1 = k1 * c - k2 * sn;
    float ko2 = k2 * c + k1 * sn;

    size_t dst = ((size_t)(b * NHEAD + h) * S_LEN + s) * HDIM;
    float hq1 = __half2float(__float2half_rn(qo1));
    float hq2 = __half2float(__float2half_rn(qo2));
    Qh[dst + i]      = __half_as_ushort(__float2half_rn(qo1));
    Qh[dst + 32 + i] = __half_as_ushort(__float2half_rn(qo2));
    Ql[dst + i]      = __half_as_ushort(__float2half_rn(qo1 - hq1));
    Ql[dst + 32 + i] = __half_as_ushort(__float2half_rn(qo2 - hq2));
    Kh[dst + i]      = __half_as_ushort(__float2half_rn(ko1));
    Kh[dst + 32 + i] = __half_as_ushort(__float2half_rn(ko2));
}

// ---------------------------------------------------------------------------
// 3b) V transpose: Vt[bh][d][s] fp16 hi only.
// ---------------------------------------------------------------------------
__global__ void __launch_bounds__(256) v_transpose_kernel(
    const float* __restrict__ qkv, unsigned short* __restrict__ Vth)
{
    __shared__ float tile[64][67];
    int st = blockIdx.x, bh = blockIdx.y;
    int b = bh >> 4, h = bh & 15;
    int t = threadIdx.x;
    #pragma unroll
    for (int it = 0; it < 4; ++it) {
        int id = t + it * 256;            // 0..1023
        int sl = id >> 4, f4 = id & 15;
        int sb = b * S_LEN + st * 64 + sl;
        float4 v = *(const float4*)(qkv + (size_t)sb * QKVD + h * 192 + 128 + f4 * 4);
        tile[sl][f4*4+0] = v.x; tile[sl][f4*4+1] = v.y;
        tile[sl][f4*4+2] = v.z; tile[sl][f4*4+3] = v.w;
    }
    __syncthreads();
    #pragma unroll
    for (int it = 0; it < 16; ++it) {
        int d  = it * 4 + (t >> 6);
        int sl = t & 63;
        float v = tile[sl][d];
        size_t dst = ((size_t)bh * HDIM + d) * S_LEN + st * 64 + sl;
        Vth[dst] = __half_as_ushort(__float2half_rn(v));
    }
}

// ---------------------------------------------------------------------------
// 4) Tensor-core flash attention, 2-term splits:
//    S = Qh*Kh + Ql*Kh;  O = Ph*Vh + Pl*Vh. Double-buffered K/V (hi only).
// ---------------------------------------------------------------------------
#define APAD 72
#define AQT (128 * APAD)   // Q tile ushorts
#define AKT (64 * APAD)    // K/V tile ushorts
#define AST (2 * AKT)      // one K/V stage: Kh,Vh
#define ATT_SMEM ((2 * AQT + 2 * AST) * 2)

__global__ void __launch_bounds__(256) attn_mma_kernel(
    const unsigned short* __restrict__ Qh, const unsigned short* __restrict__ Ql,
    const unsigned short* __restrict__ Kh, const unsigned short* __restrict__ Vth,
    unsigned short* __restrict__ Ch, unsigned short* __restrict__ Cl)
{
    extern __shared__ unsigned short sma[];
    unsigned short* sQh = sma;
    unsigned short* sQl = sma + AQT;
    unsigned short* sKV = sma + 2 * AQT;   // 2 stages of [Kh|Vh]

    int qt = blockIdx.x, bh = blockIdx.y;
    int b = bh >> 4, h = bh & 15;
    int t = threadIdx.x;
    int w = t >> 5, lane = t & 31;
    int g = lane >> 2, q = lane & 3;

    auto load_kv = [&](int st, int kt) {
        unsigned short* sg = sKV + st * AST;
        size_t kbase = ((size_t)bh * S_LEN + kt * 64) * HDIM;
        #pragma unroll
        for (int i = 0; i < 2; ++i) {
            int ch = t + i * 256;     // 0..511
            int row = ch >> 3, c = ch & 7;
            int soff = row * APAD + c * 8;
            cp16(sg + soff,       Kh + kbase + row * 64 + c * 8);
            size_t vsrc = ((size_t)bh * HDIM + row) * S_LEN + kt * 64 + c * 8;
            cp16(sg + AKT + soff, Vth + vsrc);
        }
        cp_commit();
    };

    // prologue: stage Q (hi+lo), prefetch kv tile 0
    size_t qbase = ((size_t)bh * S_LEN + qt * 128) * HDIM;
    #pragma unroll
    for (int i = 0; i < 4; ++i) {
        int ch = t + i * 256;             // 0..1023
        int row = ch >> 3, c = ch & 7;
        cp16(sQh + row * APAD + c * 8, Qh + qbase + row * 64 + c * 8);
        cp16(sQl + row * APAD + c * 8, Ql + qbase + row * 64 + c * 8);
    }
    cp_commit();
    load_kv(0, 0);
    cp_wait1();
    __syncthreads();

    uint32_t qfh[4][4], qfl[4][4];
    #pragma unroll
    for (int kk = 0; kk < 4; ++kk) {
        int r = w * 16 + (lane & 15);
        int c = kk * 16 + (lane >> 4) * 8;
        ldsm4(qfh[kk], sQh + r * APAD + c);
        ldsm4(qfl[kk], sQl + r * APAD + c);
    }

    float o[8][4];
    #pragma unroll
    for (int nt = 0; nt < 8; ++nt)
        #pragma unroll
        for (int e = 0; e < 4; ++e) o[nt][e] = 0.f;
    float mA = -1e30f, mB = -1e30f, lA = 0.f, lB = 0.f;

    int qrA = qt * 128 + w * 16 + g;
    int qmax = qt * 128 + w * 16 + 15;
    int nk = 2 * qt + 2;

    for (int kt = 0; kt < nk; ++kt) {
        cp_wait0();
        __syncthreads();
        if (kt + 1 < nk) load_kv((kt + 1) & 1, kt + 1);

        if (kt * 64 <= qmax) {
            unsigned short* sg   = sKV + (kt & 1) * AST;
            unsigned short* sKh_ = sg;
            unsigned short* sVh_ = sg + AKT;

            float s_acc[8][4];
            #pragma unroll
            for (int nt = 0; nt < 8; ++nt)
                #pragma unroll
                for (int e = 0; e < 4; ++e) s_acc[nt][e] = 0.f;

            #pragma unroll
            for (int kk = 0; kk < 4; ++kk) {
                uint32_t bh2[8][2];
                #pragma unroll
                for (int p = 0; p < 4; ++p) {
                    int r = p * 16 + ((lane >> 4) & 1) * 8 + (lane & 7);
                    int c = kk * 16 + ((lane >> 3) & 1) * 8;
                    uint32_t tmp[4];
                    ldsm4(tmp, sKh_ + r * APAD + c);
                    bh2[2*p][0] = tmp[0]; bh2[2*p][1] = tmp[1];
                    bh2[2*p+1][0] = tmp[2]; bh2[2*p+1][1] = tmp[3];
                }
                #pragma unroll
                for (int nt = 0; nt < 8; ++nt)
                    mma_f16(s_acc[nt], qfh[kk], bh2[nt]);
                #pragma unroll
                for (int nt = 0; nt < 8; ++nt)
                    mma_f16(s_acc[nt], qfl[kk], bh2[nt]);
            }

            int kb0 = kt * 64;
            if (kb0 + 63 > qrA) {
                #pragma unroll
                for (int nt = 0; nt < 8; ++nt) {
                    int colb = kb0 + nt * 8 + 2 * q;
                    if (colb     > qrA)     s_acc[nt][0] = -1e30f;
                    if (colb + 1 > qrA)     s_acc[nt][1] = -1e30f;
                    if (colb     > qrA + 8) s_acc[nt][2] = -1e30f;
                    if (colb + 1 > qrA + 8) s_acc[nt][3] = -1e30f;
                }
            }

            float mxA = -1e30f, mxB = -1e30f;
            #pragma unroll
            for (int nt = 0; nt < 8; ++nt) {
                mxA = fmaxf(mxA, fmaxf(s_acc[nt][0], s_acc[nt][1]));
                mxB = fmaxf(mxB, fmaxf(s_acc[nt][2], s_acc[nt][3]));
            }
            mxA = fmaxf(mxA, __shfl_xor_sync(0xffffffffu, mxA, 1));
            mxA = fmaxf(mxA, __shfl_xor_sync(0xffffffffu, mxA, 2));
            mxB = fmaxf(mxB, __shfl_xor_sync(0xffffffffu, mxB, 1));
            mxB = fmaxf(mxB, __shfl_xor_sync(0xffffffffu, mxB, 2));
            float mnA = fmaxf(mA, mxA), mnB = fmaxf(mB, mxB);
            float corrA = __expf(mA - mnA), corrB = __expf(mB - mnB);
            float psA = 0.f, psB = 0.f;
            #pragma unroll
            for (int nt = 0; nt < 8; ++nt) {
                s_acc[nt][0] = __expf(s_acc[nt][0] - mnA); psA += s_acc[nt][0];
                s_acc[nt][1] = __expf(s_acc[nt][1] - mnA); psA += s_acc[nt][1];
                s_acc[nt][2] = __expf(s_acc[nt][2] - mnB); psB += s_acc[nt][2];
                s_acc[nt][3] = __expf(s_acc[nt][3] - mnB); psB += s_acc[nt][3];
            }
            psA += __shfl_xor_sync(0xffffffffu, psA, 1);
            psA += __shfl_xor_sync(0xffffffffu, psA, 2);
            psB += __shfl_xor_sync(0xffffffffu, psB, 1);
            psB += __shfl_xor_sync(0xffffffffu, psB, 2);
            lA = lA * corrA + psA;  mA = mnA;
            lB = lB * corrB + psB;  mB = mnB;
            #pragma unroll
            for (int nt = 0; nt < 8; ++nt) {
                o[nt][0] *= corrA; o[nt][1] *= corrA;
                o[nt][2] *= corrB; o[nt][3] *= corrB;
            }

            #pragma unroll
            for (int kk = 0; kk < 4; ++kk) {
                int n0 = 2 * kk, n1 = 2 * kk + 1;
                uint32_t ph[4], pl[4];
                ph[0] = f2h2(s_acc[n0][0], s_acc[n0][1]);
                ph[1] = f2h2(s_acc[n0][2], s_acc[n0][3]);
                ph[2] = f2h2(s_acc[n1][0], s_acc[n1][1]);
                ph[3] = f2h2(s_acc[n1][2], s_acc[n1][3]);
                {
                    float h00 = __half2float(__ushort_as_half((unsigned short)(ph[0] & 0xffffu)));
                    float h01 = __half2float(__ushort_as_half((unsigned short)(ph[0] >> 16)));
                    float h10 = __half2float(__ushort_as_half((unsigned short)(ph[1] & 0xffffu)));
                    float h11 = __half2float(__ushort_as_half((unsigned short)(ph[1] >> 16)));
                    float h20 = __half2float(__ushort_as_half((unsigned short)(ph[2] & 0xffffu)));
                    float h21 = __half2float(__ushort_as_half((unsigned short)(ph[2] >> 16)));
                    float h30 = __half2float(__ushort_as_half((unsigned short)(ph[3] & 0xffffu)));
                    float h31 = __half2float(__ushort_as_half((unsigned short)(ph[3] >> 16)));
                    pl[0] = f2h2(s_acc[n0][0] - h00, s_acc[n0][1] - h01);
                    pl[1] = f2h2(s_acc[n0][2] - h10, s_acc[n0][3] - h11);
                    pl[2] = f2h2(s_acc[n1][0] - h20, s_acc[n1][1] - h21);
                    pl[3] = f2h2(s_acc[n1][2] - h30, s_acc[n1][3] - h31);
                }
                uint32_t vh2[8][2];
                #pragma unroll
                for (int p = 0; p < 4; ++p) {
                    int r = p * 16 + ((lane >> 4) & 1) * 8 + (lane & 7);
                    int c = kk * 16 + ((lane >> 3) & 1) * 8;
                    uint32_t tmp[4];
                    ldsm4(tmp, sVh_ + r * APAD + c);
                    vh2[2*p][0] = tmp[0]; vh2[2*p][1] = tmp[1];
                    vh2[2*p+1][0] = tmp[2]; vh2[2*p+1][1] = tmp[3];
                }
                #pragma unroll
                for (int nt = 0; nt < 8; ++nt)
                    mma_f16(o[nt], ph, vh2[nt]);
                #pragma unroll
                for (int nt = 0; nt < 8; ++nt)
                    mma_f16(o[nt], pl, vh2[nt]);
            }
        }
    }

    float invA = 1.f / lA, invB = 1.f / lB;
    int rowA = qt * 128 + w * 16 + g;
    size_t baseA = ((size_t)(b * S_LEN + rowA)) * DMODEL + h * HDIM;
    size_t baseB = baseA + (size_t)8 * DMODEL;
    #pragma unroll
    for (int nt = 0; nt < 8; ++nt) {
        int c = nt * 8 + 2 * q;
        float a0 = o[nt][0] * invA, a1 = o[nt][1] * invA;
        float b0 = o[nt][2] * invB, b1 = o[nt][3] * invB;
        float ha0 = __half2float(__float2half_rn(a0));
        float ha1 = __half2float(__float2half_rn(a1));
        float hb0 = __half2float(__float2half_rn(b0));
        float hb1 = __half2float(__float2half_rn(b1));
        *(uint32_t*)(Ch + baseA + c) = f2h2(ha0, ha1);
        *(uint32_t*)(Cl + baseA + c) = f2h2(a0 - ha0, a1 - ha1);
        *(uint32_t*)(Ch + baseB + c) = f2h2(hb0, hb1);
        *(uint32_t*)(Cl + baseB + c) = f2h2(b0 - hb0, b1 - hb1);
    }
}

// ---------------------------------------------------------------------------
// Launcher
// ---------------------------------------------------------------------------
extern "C" void kernel_launch(void* const* d_in, const int* in_sizes, int n_in,
                              void* d_out, int out_size)
{
    const float* hs     = (const float*)d_in[0];
    const float* gamma  = (const float*)d_in[1];
    const float* beta   = (const float*)d_in[2];
    const float* qkv_w  = (const float*)d_in[3];
    const float* qkv_b  = (const float*)d_in[4];
    const float* proj_w = (const float*)d_in[5];
    const float* proj_b = (const float*)d_in[6];
    float* out = (float*)d_out;

    void *pqkv, *pxh, *pxl, *pwqh, *pwph, *pch, *pcl;
    void *pqh, *pql, *pkh, *pvh;
    cudaGetSymbolAddress(&pqkv, g_qkv);
    cudaGetSymbolAddress(&pxh,  g_xh);  cudaGetSymbolAddress(&pxl,  g_xl);
    cudaGetSymbolAddress(&pwqh, g_wqh); cudaGetSymbolAddress(&pwph, g_wph);
    cudaGetSymbolAddress(&pch,  g_ch);  cudaGetSymbolAddress(&pcl,  g_cl);
    cudaGetSymbolAddress(&pqh,  g_qhh); cudaGetSymbolAddress(&pql,  g_qll);
    cudaGetSymbolAddress(&pkh,  g_khh); cudaGetSymbolAddress(&pvh,  g_vth);

    cudaFuncSetAttribute(mma_gemm_smem,
        cudaFuncAttributeMaxDynamicSharedMemorySize, GEMM_SMEM);
    cudaFuncSetAttribute(attn_mma_kernel,
        cudaFuncAttributeMaxDynamicSharedMemorySize, ATT_SMEM);

    // 1) LayerNorm + fp16 split
    ln_split_kernel<<<ROWS, 256>>>(hs, gamma, beta,
        (unsigned short*)pxh, (unsigned short*)pxl);

    // weight hi conversions
    w_f16_kernel<<<(QKVD*DMODEL/4)/256, 256>>>(qkv_w,
        (unsigned short*)pwqh, QKVD*DMODEL/4);
    w_f16_kernel<<<(DMODEL*DMODEL/4)/256, 256>>>(proj_w,
        (unsigned short*)pwph, DMODEL*DMODEL/4);

    // 2) QKV GEMM (2-term)
    mma_gemm_smem<<<dim3(QKVD/128, ROWS/128), 128, GEMM_SMEM>>>(
        (unsigned short*)pxh, (unsigned short*)pxl,
        (unsigned short*)pwqh,
        qkv_b, (float*)pqkv, ROWS, QKVD, DMODEL);

    // 3) RoPE + relayout, V transpose
    rope_convert_kernel<<<(BATCH*S_LEN*NHEAD*32)/256, 256>>>((float*)pqkv,
        (unsigned short*)pqh, (unsigned short*)pql, (unsigned short*)pkh);
    v_transpose_kernel<<<dim3(S_LEN/64, BH), 256>>>((float*)pqkv,
        (unsigned short*)pvh);

    // 4) Attention (2-term; writes fp16-split ctx)
    attn_mma_kernel<<<dim3(S_LEN/128, BH), 256, ATT_SMEM>>>(
        (unsigned short*)pqh, (unsigned short*)pql,
        (unsigned short*)pkh, (unsigned short*)pvh,
        (unsigned short*)pch, (unsigned short*)pcl);

    // 5) Output projection (2-term)
    mma_gemm_smem<<<dim3(DMODEL/128, ROWS/128), 128, GEMM_SMEM>>>(
        (unsigned short*)pch, (unsigned short*)pcl,
        (unsigned short*)pwph,
        proj_b, out, ROWS, DMODEL, DMODEL);
}

// round 9
// speedup vs baseline: 1.8394x; 1.3078x over previous
#include <cuda_runtime.h>
#include <cuda_fp16.h>
#include <math.h>
#include <stdint.h>

// Problem constants
#define BATCH   2
#define S_LEN   2048
#define DMODEL  1024
#define NHEAD   16
#define HDIM    64
#define QKVD    (3*DMODEL)     // 3072
#define ROWS    (BATCH*S_LEN)  // 4096
#define BH      (BATCH*NHEAD)  // 32

// Scratch (device globals). fp16 stored as ushort.
__device__ float g_qkv[ROWS * QKVD];                       // qkv fp32 (pre-rope)
__device__ unsigned short g_xh[ROWS * DMODEL];             // LN output hi
__device__ unsigned short g_wqh[QKVD * DMODEL];            // weights hi
__device__ unsigned short g_wph[DMODEL * DMODEL];
__device__ unsigned short g_ch[ROWS * DMODEL];             // ctx hi
__device__ unsigned short g_qhh[BH * S_LEN * HDIM], g_qll[BH * S_LEN * HDIM];
__device__ unsigned short g_khh[BH * S_LEN * HDIM];        // K hi
__device__ unsigned short g_vth[BH * HDIM * S_LEN];        // V^T hi

// ---------------------------------------------------------------------------
// helpers
// ---------------------------------------------------------------------------
__device__ __forceinline__ uint32_t f2h2(float a, float b) {
    __half2 t = __floats2half2_rn(a, b);
    return *reinterpret_cast<uint32_t*>(&t);
}
__device__ __forceinline__ uint32_t sptr(const void* p) {
    return (uint32_t)__cvta_generic_to_shared(p);
}
__device__ __forceinline__ void cp16(void* dst, const void* src) {
    asm volatile("cp.async.cg.shared.global [%0], [%1], 16;\n"
                 :: "r"(sptr(dst)), "l"(src));
}
__device__ __forceinline__ void cp_commit() { asm volatile("cp.async.commit_group;\n"); }
__device__ __forceinline__ void cp_wait0()  { asm volatile("cp.async.wait_group 0;\n"); }
__device__ __forceinline__ void cp_wait1()  { asm volatile("cp.async.wait_group 1;\n"); }

__device__ __forceinline__ void ldsm4(uint32_t* r, const void* p) {
    asm volatile("ldmatrix.sync.aligned.m8n8.x4.shared.b16 {%0,%1,%2,%3}, [%4];\n"
                 : "=r"(r[0]), "=r"(r[1]), "=r"(r[2]), "=r"(r[3]) : "r"(sptr(p)));
}
// f16 inputs, f32 accumulate
__device__ __forceinline__ void mma_f16(float* c, const uint32_t* a, const uint32_t* b) {
    asm volatile(
        "mma.sync.aligned.m16n8k16.row.col.f32.f16.f16.f32 "
        "{%0,%1,%2,%3}, {%4,%5,%6,%7}, {%8,%9}, {%0,%1,%2,%3};\n"
        : "+f"(c[0]), "+f"(c[1]), "+f"(c[2]), "+f"(c[3])
        : "r"(a[0]), "r"(a[1]), "r"(a[2]), "r"(a[3]), "r"(b[0]), "r"(b[1]));
}

// ---------------------------------------------------------------------------
// 1) LayerNorm -> fp16 hi output
// ---------------------------------------------------------------------------
__global__ void __launch_bounds__(256) ln_split_kernel(
    const float* __restrict__ x, const float* __restrict__ gamma,
    const float* __restrict__ beta, unsigned short* __restrict__ yh)
{
    __shared__ float red_s[8], red_ss[8];
    __shared__ float sh_mean, sh_inv;
    int row = blockIdx.x;
    int tid = threadIdx.x;
    const float4* xr = (const float4*)(x + (size_t)row * DMODEL);
    float4 v = xr[tid];
    float s  = v.x + v.y + v.z + v.w;
    float ss = v.x*v.x + v.y*v.y + v.z*v.z + v.w*v.w;
    #pragma unroll
    for (int off = 16; off > 0; off >>= 1) {
        s  += __shfl_down_sync(0xffffffffu, s,  off);
        ss += __shfl_down_sync(0xffffffffu, ss, off);
    }
    int wid = tid >> 5, lane = tid & 31;
    if (lane == 0) { red_s[wid] = s; red_ss[wid] = ss; }
    __syncthreads();
    if (tid == 0) {
        float S = 0.f, SS = 0.f;
        #pragma unroll
        for (int i = 0; i < 8; ++i) { S += red_s[i]; SS += red_ss[i]; }
        float mean = S * (1.f / DMODEL);
        float var  = SS * (1.f / DMODEL) - mean * mean;
        sh_mean = mean;
        sh_inv  = rsqrtf(var + 1e-5f);
    }
    __syncthreads();
    float mean = sh_mean, inv = sh_inv;
    float4 gv = ((const float4*)gamma)[tid];
    float4 bv = ((const float4*)beta)[tid];
    float o0 = (v.x - mean) * inv * gv.x + bv.x;
    float o1 = (v.y - mean) * inv * gv.y + bv.y;
    float o2 = (v.z - mean) * inv * gv.z + bv.z;
    float o3 = (v.w - mean) * inv * gv.w + bv.w;
    uint2 hv = make_uint2(f2h2(o0, o1), f2h2(o2, o3));
    *(uint2*)(yh + (size_t)row * DMODEL + tid * 4) = hv;
}

// ---------------------------------------------------------------------------
// weights: fp32 -> fp16 hi, 4 elements/thread
// ---------------------------------------------------------------------------
__global__ void __launch_bounds__(256) w_f16_kernel(
    const float* __restrict__ x, unsigned short* __restrict__ hi, int n4)
{
    int i = blockIdx.x * 256 + threadIdx.x;
    if (i >= n4) return;
    float4 v = ((const float4*)x)[i];
    uint2 hv = make_uint2(f2h2(v.x, v.y), f2h2(v.z, v.w));
    *(uint2*)(hi + (size_t)i * 4) = hv;
}

// ---------------------------------------------------------------------------
// 2) Pure-fp16 smem-staged double-buffered GEMM: C = A@B^T + bias.
//    Block 128x128, BK=32, 4 warps (2x2), warp tile 64x64.
// ---------------------------------------------------------------------------
#define GPAD 40
#define GTILE (128 * GPAD)            // ushorts per tile
#define GSTAGE (2 * GTILE)            // Ah,Bh
#define GEMM_SMEM (2 * GSTAGE * 2)    // bytes = 40960

__global__ void __launch_bounds__(128) mma_gemm_smem(
    const unsigned short* __restrict__ Ahg, const unsigned short* __restrict__ Bhg,
    const float* __restrict__ bias, float* __restrict__ C,
    int M, int N, int K)
{
    extern __shared__ unsigned short smg[];
    int t = threadIdx.x;
    int wid = t >> 5, lane = t & 31;
    int wm = wid >> 1, wn = wid & 1;
    int g = lane >> 2, q = lane & 3;
    int mb = blockIdx.y * 128, nb = blockIdx.x * 128;

    float acc[4][8][4];
    #pragma unroll
    for (int mt = 0; mt < 4; ++mt)
        #pragma unroll
        for (int nt = 0; nt < 8; ++nt)
            #pragma unroll
            for (int e = 0; e < 4; ++e) acc[mt][nt][e] = 0.f;

    const int NKB = K >> 5;

    auto load_stage = [&](int st, int k0) {
        unsigned short* base = smg + st * GSTAGE;
        #pragma unroll
        for (int i = 0; i < 4; ++i) {
            int ch = t + i * 128;          // 0..511
            int row = ch >> 2, c = ch & 3;
            int soff = row * GPAD + c * 8;
            size_t goffA = (size_t)(mb + row) * K + k0 + c * 8;
            size_t goffB = (size_t)(nb + row) * K + k0 + c * 8;
            cp16(base + soff,         Ahg + goffA);
            cp16(base + GTILE + soff, Bhg + goffB);
        }
        cp_commit();
    };

    load_stage(0, 0);

    for (int kb = 0; kb < NKB; ++kb) {
        cp_wait0();
        __syncthreads();
        if (kb + 1 < NKB) load_stage((kb + 1) & 1, (kb + 1) << 5);

        unsigned short* base = smg + (kb & 1) * GSTAGE;
        unsigned short* sAh = base;
        unsigned short* sBh = base + GTILE;

        #pragma unroll
        for (int kk = 0; kk < 2; ++kk) {
            uint32_t ah[4][4];
            #pragma unroll
            for (int mt = 0; mt < 4; ++mt) {
                int r = wm * 64 + mt * 16 + (lane & 15);
                int c = kk * 16 + (lane >> 4) * 8;
                ldsm4(ah[mt], sAh + r * GPAD + c);
            }
            uint32_t bh2[8][2];
            #pragma unroll
            for (int p = 0; p < 4; ++p) {
                int r = wn * 64 + p * 16 + ((lane >> 4) & 1) * 8 + (lane & 7);
                int c = kk * 16 + ((lane >> 3) & 1) * 8;
                uint32_t tmp[4];
                ldsm4(tmp, sBh + r * GPAD + c);
                bh2[2*p][0] = tmp[0]; bh2[2*p][1] = tmp[1];
                bh2[2*p+1][0] = tmp[2]; bh2[2*p+1][1] = tmp[3];
            }
            #pragma unroll
            for (int mt = 0; mt < 4; ++mt)
                #pragma unroll
                for (int nt = 0; nt < 8; ++nt)
                    mma_f16(acc[mt][nt], ah[mt], bh2[nt]);
        }
    }

    #pragma unroll
    for (int mt = 0; mt < 4; ++mt) {
        #pragma unroll
        for (int nt = 0; nt < 8; ++nt) {
            int r = mb + wm * 64 + mt * 16 + g;
            int c = nb + wn * 64 + nt * 8 + q * 2;
            float b0 = bias[c], b1 = bias[c + 1];
            float2 v0; v0.x = acc[mt][nt][0] + b0; v0.y = acc[mt][nt][1] + b1;
            float2 v1; v1.x = acc[mt][nt][2] + b0; v1.y = acc[mt][nt][3] + b1;
            *(float2*)(C + (size_t)r * N + c)       = v0;
            *(float2*)(C + (size_t)(r + 8) * N + c) = v1;
        }
    }
}

// ---------------------------------------------------------------------------
// 3) RoPE + head-major relayout: Q (pre-scaled) hi+lo, K hi only.
// ---------------------------------------------------------------------------
__global__ void __launch_bounds__(256) rope_convert_kernel(
    const float* __restrict__ qkv,
    unsigned short* __restrict__ Qh, unsigned short* __restrict__ Ql,
    unsigned short* __restrict__ Kh)
{
    int idx = blockIdx.x * 256 + threadIdx.x;   // B*S*H*32
    int i  = idx & 31;
    int h  = (idx >> 5) & 15;
    int sb = idx >> 9;
    int s  = sb & (S_LEN - 1);
    int b  = sb >> 11;
    const double C = 0.28782844202394213;       // ln(10000)/32
    double ang = (double)s * exp(-C * (double)i);
    double n   = rint(ang * 0.15915494309189535); // 1/(2*pi)
    float ar   = (float)(ang - n * 6.283185307179586);
    float c  = cosf(ar);
    float sn = sinf(ar);

    size_t base = (size_t)sb * QKVD + h * (3 * HDIM);
    float q1 = qkv[base + i],      q2 = qkv[base + 32 + i];
    float k1 = qkv[base + 64 + i], k2 = qkv[base + 96 + i];
    float qo1 = (q1 * c - q2 * sn) * 0.125f;
    float qo2 = (q2 * c + q1 * sn) * 0.125f;
    float ko1 = k1 * c - k2 * sn;
    float ko2 = k2 * c + k1 * sn;

    size_t dst = ((size_t)(b * NHEAD + h) * S_LEN + s) * HDIM;
    float hq1 = __half2float(__float2half_rn(qo1));
    float hq2 = __half2float(__float2half_rn(qo2));
    Qh[dst + i]      = __half_as_ushort(__float2half_rn(qo1));
    Qh[dst + 32 + i] = __half_as_ushort(__float2half_rn(qo2));
    Ql[dst + i]      = __half_as_ushort(__float2half_rn(qo1 - hq1));
    Ql[dst + 32 + i] = __half_as_ushort(__float2half_rn(qo2 - hq2));
    Kh[dst + i]      = __half_as_ushort(__float2half_rn(ko1));
    Kh[dst + 32 + i] = __half_as_ushort(__float2half_rn(ko2));
}

// ---------------------------------------------------------------------------
// 3b) V transpose: Vt[bh][d][s] fp16 hi only.
// ---------------------------------------------------------------------------
__global__ void __launch_bounds__(256) v_transpose_kernel(
    const float* __restrict__ qkv, unsigned short* __restrict__ Vth)
{
    __shared__ float tile[64][67];
    int st = blockIdx.x, bh = blockIdx.y;
    int b = bh >> 4, h = bh & 15;
    int t = threadIdx.x;
    #pragma unroll
    for (int it = 0; it < 4; ++it) {
        int id = t + it * 256;            // 0..1023
        int sl = id >> 4, f4 = id & 15;
        int sb = b * S_LEN + st * 64 + sl;
        float4 v = *(const float4*)(qkv + (size_t)sb * QKVD + h * 192 + 128 + f4 * 4);
        tile[sl][f4*4+0] = v.x; tile[sl][f4*4+1] = v.y;
        tile[sl][f4*4+2] = v.z; tile[sl][f4*4+3] = v.w;
    }
    __syncthreads();
    #pragma unroll
    for (int it = 0; it < 16; ++it) {
        int d  = it * 4 + (t >> 6);
        int sl = t & 63;
        float v = tile[sl][d];
        size_t dst = ((size_t)bh * HDIM + d) * S_LEN + st * 64 + sl;
        Vth[dst] = __half_as_ushort(__float2half_rn(v));
    }
}

// ---------------------------------------------------------------------------
// 4) Tensor-core flash attention, 2-term splits (unchanged math):
//    S = Qh*Kh + Ql*Kh;  O = Ph*Vh + Pl*Vh. Double-buffered K/V (hi only).
//    qt reversed for wave load balance; ctx written fp16 hi only.
// ---------------------------------------------------------------------------
#define APAD 72
#define AQT (128 * APAD)   // Q tile ushorts
#define AKT (64 * APAD)    // K/V tile ushorts
#define AST (2 * AKT)      // one K/V stage: Kh,Vh
#define ATT_SMEM ((2 * AQT + 2 * AST) * 2)

__global__ void __launch_bounds__(256) attn_mma_kernel(
    const unsigned short* __restrict__ Qh, const unsigned short* __restrict__ Ql,
    const unsigned short* __restrict__ Kh, const unsigned short* __restrict__ Vth,
    unsigned short* __restrict__ Ch)
{
    extern __shared__ unsigned short sma[];
    unsigned short* sQh = sma;
    unsigned short* sQl = sma + AQT;
    unsigned short* sKV = sma + 2 * AQT;   // 2 stages of [Kh|Vh]

    int qt = gridDim.x - 1 - blockIdx.x;   // biggest workloads launch first
    int bh = blockIdx.y;
    int b = bh >> 4, h = bh & 15;
    int t = threadIdx.x;
    int w = t >> 5, lane = t & 31;
    int g = lane >> 2, q = lane & 3;

    auto load_kv = [&](int st, int kt) {
        unsigned short* sg = sKV + st * AST;
        size_t kbase = ((size_t)bh * S_LEN + kt * 64) * HDIM;
        #pragma unroll
        for (int i = 0; i < 2; ++i) {
            int ch = t + i * 256;     // 0..511
            int row = ch >> 3, c = ch & 7;
            int soff = row * APAD + c * 8;
            cp16(sg + soff,       Kh + kbase + row * 64 + c * 8);
            size_t vsrc = ((size_t)bh * HDIM + row) * S_LEN + kt * 64 + c * 8;
            cp16(sg + AKT + soff, Vth + vsrc);
        }
        cp_commit();
    };

    // prologue: stage Q (hi+lo), prefetch kv tile 0
    size_t qbase = ((size_t)bh * S_LEN + qt * 128) * HDIM;
    #pragma unroll
    for (int i = 0; i < 4; ++i) {
        int ch = t + i * 256;             // 0..1023
        int row = ch >> 3, c = ch & 7;
        cp16(sQh + row * APAD + c * 8, Qh + qbase + row * 64 + c * 8);
        cp16(sQl + row * APAD + c * 8, Ql + qbase + row * 64 + c * 8);
    }
    cp_commit();
    load_kv(0, 0);
    cp_wait1();
    __syncthreads();

    uint32_t qfh[4][4], qfl[4][4];
    #pragma unroll
    for (int kk = 0; kk < 4; ++kk) {
        int r = w * 16 + (lane & 15);
        int c = kk * 16 + (lane >> 4) * 8;
        ldsm4(qfh[kk], sQh + r * APAD + c);
        ldsm4(qfl[kk], sQl + r * APAD + c);
    }

    float o[8][4];
    #pragma unroll
    for (int nt = 0; nt < 8; ++nt)
        #pragma unroll
        for (int e = 0; e < 4; ++e) o[nt][e] = 0.f;
    float mA = -1e30f, mB = -1e30f, lA = 0.f, lB = 0.f;

    int qrA = qt * 128 + w * 16 + g;
    int qmax = qt * 128 + w * 16 + 15;
    int nk = 2 * qt + 2;

    for (int kt = 0; kt < nk; ++kt) {
        cp_wait0();
        __syncthreads();
        if (kt + 1 < nk) load_kv((kt + 1) & 1, kt + 1);

        if (kt * 64 <= qmax) {
            unsigned short* sg   = sKV + (kt & 1) * AST;
            unsigned short* sKh_ = sg;
            unsigned short* sVh_ = sg + AKT;

            float s_acc[8][4];
            #pragma unroll
            for (int nt = 0; nt < 8; ++nt)
                #pragma unroll
                for (int e = 0; e < 4; ++e) s_acc[nt][e] = 0.f;

            #pragma unroll
            for (int kk = 0; kk < 4; ++kk) {
                uint32_t bh2[8][2];
                #pragma unroll
                for (int p = 0; p < 4; ++p) {
                    int r = p * 16 + ((lane >> 4) & 1) * 8 + (lane & 7);
                    int c = kk * 16 + ((lane >> 3) & 1) * 8;
                    uint32_t tmp[4];
                    ldsm4(tmp, sKh_ + r * APAD + c);
                    bh2[2*p][0] = tmp[0]; bh2[2*p][1] = tmp[1];
                    bh2[2*p+1][0] = tmp[2]; bh2[2*p+1][1] = tmp[3];
                }
                #pragma unroll
                for (int nt = 0; nt < 8; ++nt)
                    mma_f16(s_acc[nt], qfh[kk], bh2[nt]);
                #pragma unroll
                for (int nt = 0; nt < 8; ++nt)
                    mma_f16(s_acc[nt], qfl[kk], bh2[nt]);
            }

            int kb0 = kt * 64;
            if (kb0 + 63 > qrA) {
                #pragma unroll
                for (int nt = 0; nt < 8; ++nt) {
                    int colb = kb0 + nt * 8 + 2 * q;
                    if (colb     > qrA)     s_acc[nt][0] = -1e30f;
                    if (colb + 1 > qrA)     s_acc[nt][1] = -1e30f;
                    if (colb     > qrA + 8) s_acc[nt][2] = -1e30f;
                    if (colb + 1 > qrA + 8) s_acc[nt][3] = -1e30f;
                }
            }

            float mxA = -1e30f, mxB = -1e30f;
            #pragma unroll
            for (int nt = 0; nt < 8; ++nt) {
                mxA = fmaxf(mxA, fmaxf(s_acc[nt][0], s_acc[nt][1]));
                mxB = fmaxf(mxB, fmaxf(s_acc[nt][2], s_acc[nt][3]));
            }
            mxA = fmaxf(mxA, __shfl_xor_sync(0xffffffffu, mxA, 1));
            mxA = fmaxf(mxA, __shfl_xor_sync(0xffffffffu, mxA, 2));
            mxB = fmaxf(mxB, __shfl_xor_sync(0xffffffffu, mxB, 1));
            mxB = fmaxf(mxB, __shfl_xor_sync(0xffffffffu, mxB, 2));
            float mnA = fmaxf(mA, mxA), mnB = fmaxf(mB, mxB);
            float corrA = __expf(mA - mnA), corrB = __expf(mB - mnB);
            float psA = 0.f, psB = 0.f;
            #pragma unroll
            for (int nt = 0; nt < 8; ++nt) {
                s_acc[nt][0] = __expf(s_acc[nt][0] - mnA); psA += s_acc[nt][0];
                s_acc[nt][1] = __expf(s_acc[nt][1] - mnA); psA += s_acc[nt][1];
                s_acc[nt][2] = __expf(s_acc[nt][2] - mnB); psB += s_acc[nt][2];
                s_acc[nt][3] = __expf(s_acc[nt][3] - mnB); psB += s_acc[nt][3];
            }
            psA += __shfl_xor_sync(0xffffffffu, psA, 1);
            psA += __shfl_xor_sync(0xffffffffu, psA, 2);
            psB += __shfl_xor_sync(0xffffffffu, psB, 1);
            psB += __shfl_xor_sync(0xffffffffu, psB, 2);
            lA = lA * corrA + psA;  mA = mnA;
            lB = lB * corrB + psB;  mB = mnB;
            #pragma unroll
            for (int nt = 0; nt < 8; ++nt) {
                o[nt][0] *= corrA; o[nt][1] *= corrA;
                o[nt][2] *= corrB; o[nt][3] *= corrB;
            }

            #pragma unroll
            for (int kk = 0; kk < 4; ++kk) {
                int n0 = 2 * kk, n1 = 2 * kk + 1;
                uint32_t ph[4], pl[4];
                ph[0] = f2h2(s_acc[n0][0], s_acc[n0][1]);
                ph[1] = f2h2(s_acc[n0][2], s_acc[n0][3]);
                ph[2] = f2h2(s_acc[n1][0], s_acc[n1][1]);
                ph[3] = f2h2(s_acc[n1][2], s_acc[n1][3]);
                {
                    float h00 = __half2float(__ushort_as_half((unsigned short)(ph[0] & 0xffffu)));
                    float h01 = __half2float(__ushort_as_half((unsigned short)(ph[0] >> 16)));
                    float h10 = __half2float(__ushort_as_half((unsigned short)(ph[1] & 0xffffu)));
                    float h11 = __half2float(__ushort_as_half((unsigned short)(ph[1] >> 16)));
                    float h20 = __half2float(__ushort_as_half((unsigned short)(ph[2] & 0xffffu)));
                    float h21 = __half2float(__ushort_as_half((unsigned short)(ph[2] >> 16)));
                    float h30 = __half2float(__ushort_as_half((unsigned short)(ph[3] & 0xffffu)));
                    float h31 = __half2float(__ushort_as_half((unsigned short)(ph[3] >> 16)));
                    pl[0] = f2h2(s_acc[n0][0] - h00, s_acc[n0][1] - h01);
                    pl[1] = f2h2(s_acc[n0][2] - h10, s_acc[n0][3] - h11);
                    pl[2] = f2h2(s_acc[n1][0] - h20, s_acc[n1][1] - h21);
                    pl[3] = f2h2(s_acc[n1][2] - h30, s_acc[n1][3] - h31);
                }
                uint32_t vh2[8][2];
                #pragma unroll
                for (int p = 0; p < 4; ++p) {
                    int r = p * 16 + ((lane >> 4) & 1) * 8 + (lane & 7);
                    int c = kk * 16 + ((lane >> 3) & 1) * 8;
                    uint32_t tmp[4];
                    ldsm4(tmp, sVh_ + r * APAD + c);
                    vh2[2*p][0] = tmp[0]; vh2[2*p][1] = tmp[1];
                    vh2[2*p+1][0] = tmp[2]; vh2[2*p+1][1] = tmp[3];
                }
                #pragma unroll
                for (int nt = 0; nt < 8; ++nt)
                    mma_f16(o[nt], ph, vh2[nt]);
                #pragma unroll
                for (int nt = 0; nt < 8; ++nt)
                    mma_f16(o[nt], pl, vh2[nt]);
            }
        }
    }

    float invA = 1.f / lA, invB = 1.f / lB;
    int rowA = qt * 128 + w * 16 + g;
    size_t baseA = ((size_t)(b * S_LEN + rowA)) * DMODEL + h * HDIM;
    size_t baseB = baseA + (size_t)8 * DMODEL;
    #pragma unroll
    for (int nt = 0; nt < 8; ++nt) {
        int c = nt * 8 + 2 * q;
        float a0 = o[nt][0] * invA, a1 = o[nt][1] * invA;
        float b0 = o[nt][2] * invB, b1 = o[nt][3] * invB;
        *(uint32_t*)(Ch + baseA + c) = f2h2(a0, a1);
        *(uint32_t*)(Ch + baseB + c) = f2h2(b0, b1);
    }
}

// ---------------------------------------------------------------------------
// Launcher
// ---------------------------------------------------------------------------
extern "C" void kernel_launch(void* const* d_in, const int* in_sizes, int n_in,
                              void* d_out, int out_size)
{
    const float* hs     = (const float*)d_in[0];
    const float* gamma  = (const float*)d_in[1];
    const float* beta   = (const float*)d_in[2];
    const float* qkv_w  = (const float*)d_in[3];
    const float* qkv_b  = (const float*)d_in[4];
    const float* proj_w = (const float*)d_in[5];
    const float* proj_b = (const float*)d_in[6];
    float* out = (float*)d_out;

    void *pqkv, *pxh, *pwqh, *pwph, *pch;
    void *pqh, *pql, *pkh, *pvh;
    cudaGetSymbolAddress(&pqkv, g_qkv);
    cudaGetSymbolAddress(&pxh,  g_xh);
    cudaGetSymbolAddress(&pwqh, g_wqh); cudaGetSymbolAddress(&pwph, g_wph);
    cudaGetSymbolAddress(&pch,  g_ch);
    cudaGetSymbolAddress(&pqh,  g_qhh); cudaGetSymbolAddress(&pql,  g_qll);
    cudaGetSymbolAddress(&pkh,  g_khh); cudaGetSymbolAddress(&pvh,  g_vth);

    cudaFuncSetAttribute(mma_gemm_smem,
        cudaFuncAttributeMaxDynamicSharedMemorySize, GEMM_SMEM);
    cudaFuncSetAttribute(attn_mma_kernel,
        cudaFuncAttributeMaxDynamicSharedMemorySize, ATT_SMEM);

    // 1) LayerNorm -> fp16
    ln_split_kernel<<<ROWS, 256>>>(hs, gamma, beta, (unsigned short*)pxh);

    // weight hi conversions
    w_f16_kernel<<<(QKVD*DMODEL/4)/256, 256>>>(qkv_w,
        (unsigned short*)pwqh, QKVD*DMODEL/4);
    w_f16_kernel<<<(DMODEL*DMODEL/4)/256, 256>>>(proj_w,
        (unsigned short*)pwph, DMODEL*DMODEL/4);

    // 2) QKV GEMM (pure fp16)
    mma_gemm_smem<<<dim3(QKVD/128, ROWS/128), 128, GEMM_SMEM>>>(
        (unsigned short*)pxh, (unsigned short*)pwqh,
        qkv_b, (float*)pqkv, ROWS, QKVD, DMODEL);

    // 3) RoPE + relayout, V transpose
    rope_convert_kernel<<<(BATCH*S_LEN*NHEAD*32)/256, 256>>>((float*)pqkv,
        (unsigned short*)pqh, (unsigned short*)pql, (unsigned short*)pkh);
    v_transpose_kernel<<<dim3(S_LEN/64, BH), 256>>>((float*)pqkv,
        (unsigned short*)pvh);

    // 4) Attention (2-term; writes fp16 ctx)
    attn_mma_kernel<<<dim3(S_LEN/128, BH), 256, ATT_SMEM>>>(
        (unsigned short*)pqh, (unsigned short*)pql,
        (unsigned short*)pkh, (unsigned short*)pvh,
        (unsigned short*)pch);

    // 5) Output projection (pure fp16)
    mma_gemm_smem<<<dim3(DMODEL/128, ROWS/128), 128, GEMM_SMEM>>>(
        (unsigned short*)pch, (unsigned short*)pwph,
        proj_b, out, ROWS, DMODEL, DMODEL);
}

// round 10
// speedup vs baseline: 2.1315x; 1.1588x over previous
#include <cuda_runtime.h>
#include <cuda_fp16.h>
#include <math.h>
#include <stdint.h>

// Problem constants
#define BATCH   2
#define S_LEN   2048
#define DMODEL  1024
#define NHEAD   16
#define HDIM    64
#define QKVD    (3*DMODEL)     // 3072
#define ROWS    (BATCH*S_LEN)  // 4096
#define BH      (BATCH*NHEAD)  // 32

// Scratch (device globals). fp16 stored as ushort.
__device__ float g_qkv[ROWS * QKVD];                       // qkv fp32 (pre-rope)
__device__ unsigned short g_xh[ROWS * DMODEL];             // LN output
__device__ unsigned short g_wqh[QKVD * DMODEL];            // weights
__device__ unsigned short g_wph[DMODEL * DMODEL];
__device__ unsigned short g_ch[ROWS * DMODEL];             // ctx
__device__ unsigned short g_qhh[BH * S_LEN * HDIM];        // Q (post-rope, scaled)
__device__ unsigned short g_khh[BH * S_LEN * HDIM];        // K
__device__ unsigned short g_vth[BH * HDIM * S_LEN];        // V^T

// ---------------------------------------------------------------------------
// helpers
// ---------------------------------------------------------------------------
__device__ __forceinline__ uint32_t f2h2(float a, float b) {
    __half2 t = __floats2half2_rn(a, b);
    return *reinterpret_cast<uint32_t*>(&t);
}
__device__ __forceinline__ uint32_t sptr(const void* p) {
    return (uint32_t)__cvta_generic_to_shared(p);
}
__device__ __forceinline__ void cp16(void* dst, const void* src) {
    asm volatile("cp.async.cg.shared.global [%0], [%1], 16;\n"
                 :: "r"(sptr(dst)), "l"(src));
}
__device__ __forceinline__ void cp_commit() { asm volatile("cp.async.commit_group;\n"); }
__device__ __forceinline__ void cp_wait0()  { asm volatile("cp.async.wait_group 0;\n"); }
__device__ __forceinline__ void cp_wait1()  { asm volatile("cp.async.wait_group 1;\n"); }

__device__ __forceinline__ void ldsm4(uint32_t* r, const void* p) {
    asm volatile("ldmatrix.sync.aligned.m8n8.x4.shared.b16 {%0,%1,%2,%3}, [%4];\n"
                 : "=r"(r[0]), "=r"(r[1]), "=r"(r[2]), "=r"(r[3]) : "r"(sptr(p)));
}
// f16 inputs, f32 accumulate
__device__ __forceinline__ void mma_f16(float* c, const uint32_t* a, const uint32_t* b) {
    asm volatile(
        "mma.sync.aligned.m16n8k16.row.col.f32.f16.f16.f32 "
        "{%0,%1,%2,%3}, {%4,%5,%6,%7}, {%8,%9}, {%0,%1,%2,%3};\n"
        : "+f"(c[0]), "+f"(c[1]), "+f"(c[2]), "+f"(c[3])
        : "r"(a[0]), "r"(a[1]), "r"(a[2]), "r"(a[3]), "r"(b[0]), "r"(b[1]));
}

// ---------------------------------------------------------------------------
// 1) LayerNorm -> fp16 output
// ---------------------------------------------------------------------------
__global__ void __launch_bounds__(256) ln_split_kernel(
    const float* __restrict__ x, const float* __restrict__ gamma,
    const float* __restrict__ beta, unsigned short* __restrict__ yh)
{
    __shared__ float red_s[8], red_ss[8];
    __shared__ float sh_mean, sh_inv;
    int row = blockIdx.x;
    int tid = threadIdx.x;
    const float4* xr = (const float4*)(x + (size_t)row * DMODEL);
    float4 v = xr[tid];
    float s  = v.x + v.y + v.z + v.w;
    float ss = v.x*v.x + v.y*v.y + v.z*v.z + v.w*v.w;
    #pragma unroll
    for (int off = 16; off > 0; off >>= 1) {
        s  += __shfl_down_sync(0xffffffffu, s,  off);
        ss += __shfl_down_sync(0xffffffffu, ss, off);
    }
    int wid = tid >> 5, lane = tid & 31;
    if (lane == 0) { red_s[wid] = s; red_ss[wid] = ss; }
    __syncthreads();
    if (tid == 0) {
        float S = 0.f, SS = 0.f;
        #pragma unroll
        for (int i = 0; i < 8; ++i) { S += red_s[i]; SS += red_ss[i]; }
        float mean = S * (1.f / DMODEL);
        float var  = SS * (1.f / DMODEL) - mean * mean;
        sh_mean = mean;
        sh_inv  = rsqrtf(var + 1e-5f);
    }
    __syncthreads();
    float mean = sh_mean, inv = sh_inv;
    float4 gv = ((const float4*)gamma)[tid];
    float4 bv = ((const float4*)beta)[tid];
    float o0 = (v.x - mean) * inv * gv.x + bv.x;
    float o1 = (v.y - mean) * inv * gv.y + bv.y;
    float o2 = (v.z - mean) * inv * gv.z + bv.z;
    float o3 = (v.w - mean) * inv * gv.w + bv.w;
    uint2 hv = make_uint2(f2h2(o0, o1), f2h2(o2, o3));
    *(uint2*)(yh + (size_t)row * DMODEL + tid * 4) = hv;
}

// ---------------------------------------------------------------------------
// weights: fp32 -> fp16, 4 elements/thread
// ---------------------------------------------------------------------------
__global__ void __launch_bounds__(256) w_f16_kernel(
    const float* __restrict__ x, unsigned short* __restrict__ hi, int n4)
{
    int i = blockIdx.x * 256 + threadIdx.x;
    if (i >= n4) return;
    float4 v = ((const float4*)x)[i];
    uint2 hv = make_uint2(f2h2(v.x, v.y), f2h2(v.z, v.w));
    *(uint2*)(hi + (size_t)i * 4) = hv;
}

// ---------------------------------------------------------------------------
// 2) Pure-fp16 smem-staged double-buffered GEMM: C = A@B^T + bias.
//    Block 128x128, BK=32, 4 warps (2x2), warp tile 64x64.
// ---------------------------------------------------------------------------
#define GPAD 40
#define GTILE (128 * GPAD)            // ushorts per tile
#define GSTAGE (2 * GTILE)            // Ah,Bh
#define GEMM_SMEM (2 * GSTAGE * 2)    // bytes = 40960

__global__ void __launch_bounds__(128) mma_gemm_smem(
    const unsigned short* __restrict__ Ahg, const unsigned short* __restrict__ Bhg,
    const float* __restrict__ bias, float* __restrict__ C,
    int M, int N, int K)
{
    extern __shared__ unsigned short smg[];
    int t = threadIdx.x;
    int wid = t >> 5, lane = t & 31;
    int wm = wid >> 1, wn = wid & 1;
    int g = lane >> 2, q = lane & 3;
    int mb = blockIdx.y * 128, nb = blockIdx.x * 128;

    float acc[4][8][4];
    #pragma unroll
    for (int mt = 0; mt < 4; ++mt)
        #pragma unroll
        for (int nt = 0; nt < 8; ++nt)
            #pragma unroll
            for (int e = 0; e < 4; ++e) acc[mt][nt][e] = 0.f;

    const int NKB = K >> 5;

    auto load_stage = [&](int st, int k0) {
        unsigned short* base = smg + st * GSTAGE;
        #pragma unroll
        for (int i = 0; i < 4; ++i) {
            int ch = t + i * 128;          // 0..511
            int row = ch >> 2, c = ch & 3;
            int soff = row * GPAD + c * 8;
            size_t goffA = (size_t)(mb + row) * K + k0 + c * 8;
            size_t goffB = (size_t)(nb + row) * K + k0 + c * 8;
            cp16(base + soff,         Ahg + goffA);
            cp16(base + GTILE + soff, Bhg + goffB);
        }
        cp_commit();
    };

    load_stage(0, 0);

    for (int kb = 0; kb < NKB; ++kb) {
        cp_wait0();
        __syncthreads();
        if (kb + 1 < NKB) load_stage((kb + 1) & 1, (kb + 1) << 5);

        unsigned short* base = smg + (kb & 1) * GSTAGE;
        unsigned short* sAh = base;
        unsigned short* sBh = base + GTILE;

        #pragma unroll
        for (int kk = 0; kk < 2; ++kk) {
            uint32_t ah[4][4];
            #pragma unroll
            for (int mt = 0; mt < 4; ++mt) {
                int r = wm * 64 + mt * 16 + (lane & 15);
                int c = kk * 16 + (lane >> 4) * 8;
                ldsm4(ah[mt], sAh + r * GPAD + c);
            }
            uint32_t bh2[8][2];
            #pragma unroll
            for (int p = 0; p < 4; ++p) {
                int r = wn * 64 + p * 16 + ((lane >> 4) & 1) * 8 + (lane & 7);
                int c = kk * 16 + ((lane >> 3) & 1) * 8;
                uint32_t tmp[4];
                ldsm4(tmp, sBh + r * GPAD + c);
                bh2[2*p][0] = tmp[0]; bh2[2*p][1] = tmp[1];
                bh2[2*p+1][0] = tmp[2]; bh2[2*p+1][1] = tmp[3];
            }
            #pragma unroll
            for (int mt = 0; mt < 4; ++mt)
                #pragma unroll
                for (int nt = 0; nt < 8; ++nt)
                    mma_f16(acc[mt][nt], ah[mt], bh2[nt]);
        }
    }

    #pragma unroll
    for (int mt = 0; mt < 4; ++mt) {
        #pragma unroll
        for (int nt = 0; nt < 8; ++nt) {
            int r = mb + wm * 64 + mt * 16 + g;
            int c = nb + wn * 64 + nt * 8 + q * 2;
            float b0 = bias[c], b1 = bias[c + 1];
            float2 v0; v0.x = acc[mt][nt][0] + b0; v0.y = acc[mt][nt][1] + b1;
            float2 v1; v1.x = acc[mt][nt][2] + b0; v1.y = acc[mt][nt][3] + b1;
            *(float2*)(C + (size_t)r * N + c)       = v0;
            *(float2*)(C + (size_t)(r + 8) * N + c) = v1;
        }
    }
}

// ---------------------------------------------------------------------------
// 3) RoPE + head-major relayout: Q (pre-scaled) and K, fp16.
// ---------------------------------------------------------------------------
__global__ void __launch_bounds__(256) rope_convert_kernel(
    const float* __restrict__ qkv,
    unsigned short* __restrict__ Qh, unsigned short* __restrict__ Kh)
{
    int idx = blockIdx.x * 256 + threadIdx.x;   // B*S*H*32
    int i  = idx & 31;
    int h  = (idx >> 5) & 15;
    int sb = idx >> 9;
    int s  = sb & (S_LEN - 1);
    int b  = sb >> 11;
    const double C = 0.28782844202394213;       // ln(10000)/32
    double ang = (double)s * exp(-C * (double)i);
    double n   = rint(ang * 0.15915494309189535); // 1/(2*pi)
    float ar   = (float)(ang - n * 6.283185307179586);
    float c  = cosf(ar);
    float sn = sinf(ar);

    size_t base = (size_t)sb * QKVD + h * (3 * HDIM);
    float q1 = qkv[base + i],      q2 = qkv[base + 32 + i];
    float k1 = qkv[base + 64 + i], k2 = qkv[base + 96 + i];
    float qo1 = (q1 * c - q2 * sn) * 0.125f;
    float qo2 = (q2 * c + q1 * sn) * 0.125f;
    float ko1 = k1 * c - k2 * sn;
    float ko2 = k2 * c + k1 * sn;

    size_t dst = ((size_t)(b * NHEAD + h) * S_LEN + s) * HDIM;
    Qh[dst + i]      = __half_as_ushort(__float2half_rn(qo1));
    Qh[dst + 32 + i] = __half_as_ushort(__float2half_rn(qo2));
    Kh[dst + i]      = __half_as_ushort(__float2half_rn(ko1));
    Kh[dst + 32 + i] = __half_as_ushort(__float2half_rn(ko2));
}

// ---------------------------------------------------------------------------
// 3b) V transpose: Vt[bh][d][s] fp16.
// ---------------------------------------------------------------------------
__global__ void __launch_bounds__(256) v_transpose_kernel(
    const float* __restrict__ qkv, unsigned short* __restrict__ Vth)
{
    __shared__ float tile[64][67];
    int st = blockIdx.x, bh = blockIdx.y;
    int b = bh >> 4, h = bh & 15;
    int t = threadIdx.x;
    #pragma unroll
    for (int it = 0; it < 4; ++it) {
        int id = t + it * 256;            // 0..1023
        int sl = id >> 4, f4 = id & 15;
        int sb = b * S_LEN + st * 64 + sl;
        float4 v = *(const float4*)(qkv + (size_t)sb * QKVD + h * 192 + 128 + f4 * 4);
        tile[sl][f4*4+0] = v.x; tile[sl][f4*4+1] = v.y;
        tile[sl][f4*4+2] = v.z; tile[sl][f4*4+3] = v.w;
    }
    __syncthreads();
    #pragma unroll
    for (int it = 0; it < 16; ++it) {
        int d  = it * 4 + (t >> 6);
        int sl = t & 63;
        float v = tile[sl][d];
        size_t dst = ((size_t)bh * HDIM + d) * S_LEN + st * 64 + sl;
        Vth[dst] = __half_as_ushort(__float2half_rn(v));
    }
}

// ---------------------------------------------------------------------------
// 4) Pure-fp16 tensor-core flash attention (f32 accum + fp32 softmax).
//    Double-buffered K/V; qt reversed for wave balance.
// ---------------------------------------------------------------------------
#define APAD 72
#define AQT (128 * APAD)   // Q tile ushorts
#define AKT (64 * APAD)    // K/V tile ushorts
#define AST (2 * AKT)      // one K/V stage: Kh,Vh
#define ATT_SMEM ((AQT + 2 * AST) * 2)

__global__ void __launch_bounds__(256) attn_mma_kernel(
    const unsigned short* __restrict__ Qh,
    const unsigned short* __restrict__ Kh, const unsigned short* __restrict__ Vth,
    unsigned short* __restrict__ Ch)
{
    extern __shared__ unsigned short sma[];
    unsigned short* sQh = sma;
    unsigned short* sKV = sma + AQT;   // 2 stages of [Kh|Vh]

    int qt = gridDim.x - 1 - blockIdx.x;   // biggest workloads launch first
    int bh = blockIdx.y;
    int b = bh >> 4, h = bh & 15;
    int t = threadIdx.x;
    int w = t >> 5, lane = t & 31;
    int g = lane >> 2, q = lane & 3;

    auto load_kv = [&](int st, int kt) {
        unsigned short* sg = sKV + st * AST;
        size_t kbase = ((size_t)bh * S_LEN + kt * 64) * HDIM;
        #pragma unroll
        for (int i = 0; i < 2; ++i) {
            int ch = t + i * 256;     // 0..511
            int row = ch >> 3, c = ch & 7;
            int soff = row * APAD + c * 8;
            cp16(sg + soff,       Kh + kbase + row * 64 + c * 8);
            size_t vsrc = ((size_t)bh * HDIM + row) * S_LEN + kt * 64 + c * 8;
            cp16(sg + AKT + soff, Vth + vsrc);
        }
        cp_commit();
    };

    // prologue: stage Q, prefetch kv tile 0
    size_t qbase = ((size_t)bh * S_LEN + qt * 128) * HDIM;
    #pragma unroll
    for (int i = 0; i < 4; ++i) {
        int ch = t + i * 256;             // 0..1023
        int row = ch >> 3, c = ch & 7;
        cp16(sQh + row * APAD + c * 8, Qh + qbase + row * 64 + c * 8);
    }
    cp_commit();
    load_kv(0, 0);
    cp_wait1();
    __syncthreads();

    uint32_t qfh[4][4];
    #pragma unroll
    for (int kk = 0; kk < 4; ++kk) {
        int r = w * 16 + (lane & 15);
        int c = kk * 16 + (lane >> 4) * 8;
        ldsm4(qfh[kk], sQh + r * APAD + c);
    }

    float o[8][4];
    #pragma unroll
    for (int nt = 0; nt < 8; ++nt)
        #pragma unroll
        for (int e = 0; e < 4; ++e) o[nt][e] = 0.f;
    float mA = -1e30f, mB = -1e30f, lA = 0.f, lB = 0.f;

    int qrA = qt * 128 + w * 16 + g;
    int qmax = qt * 128 + w * 16 + 15;
    int nk = 2 * qt + 2;

    for (int kt = 0; kt < nk; ++kt) {
        cp_wait0();
        __syncthreads();
        if (kt + 1 < nk) load_kv((kt + 1) & 1, kt + 1);

        if (kt * 64 <= qmax) {
            unsigned short* sg   = sKV + (kt & 1) * AST;
            unsigned short* sKh_ = sg;
            unsigned short* sVh_ = sg + AKT;

            float s_acc[8][4];
            #pragma unroll
            for (int nt = 0; nt < 8; ++nt)
                #pragma unroll
                for (int e = 0; e < 4; ++e) s_acc[nt][e] = 0.f;

            #pragma unroll
            for (int kk = 0; kk < 4; ++kk) {
                uint32_t bh2[8][2];
                #pragma unroll
                for (int p = 0; p < 4; ++p) {
                    int r = p * 16 + ((lane >> 4) & 1) * 8 + (lane & 7);
                    int c = kk * 16 + ((lane >> 3) & 1) * 8;
                    uint32_t tmp[4];
                    ldsm4(tmp, sKh_ + r * APAD + c);
                    bh2[2*p][0] = tmp[0]; bh2[2*p][1] = tmp[1];
                    bh2[2*p+1][0] = tmp[2]; bh2[2*p+1][1] = tmp[3];
                }
                #pragma unroll
                for (int nt = 0; nt < 8; ++nt)
                    mma_f16(s_acc[nt], qfh[kk], bh2[nt]);
            }

            int kb0 = kt * 64;
            if (kb0 + 63 > qrA) {
                #pragma unroll
                for (int nt = 0; nt < 8; ++nt) {
                    int colb = kb0 + nt * 8 + 2 * q;
                    if (colb     > qrA)     s_acc[nt][0] = -1e30f;
                    if (colb + 1 > qrA)     s_acc[nt][1] = -1e30f;
                    if (colb     > qrA + 8) s_acc[nt][2] = -1e30f;
                    if (colb + 1 > qrA + 8) s_acc[nt][3] = -1e30f;
                }
            }

            float mxA = -1e30f, mxB = -1e30f;
            #pragma unroll
            for (int nt = 0; nt < 8; ++nt) {
                mxA = fmaxf(mxA, fmaxf(s_acc[nt][0], s_acc[nt][1]));
                mxB = fmaxf(mxB, fmaxf(s_acc[nt][2], s_acc[nt][3]));
            }
            mxA = fmaxf(mxA, __shfl_xor_sync(0xffffffffu, mxA, 1));
            mxA = fmaxf(mxA, __shfl_xor_sync(0xffffffffu, mxA, 2));
            mxB = fmaxf(mxB, __shfl_xor_sync(0xffffffffu, mxB, 1));
            mxB = fmaxf(mxB, __shfl_xor_sync(0xffffffffu, mxB, 2));
            float mnA = fmaxf(mA, mxA), mnB = fmaxf(mB, mxB);
            float corrA = __expf(mA - mnA), corrB = __expf(mB - mnB);
            float psA = 0.f, psB = 0.f;
            #pragma unroll
            for (int nt = 0; nt < 8; ++nt) {
                s_acc[nt][0] = __expf(s_acc[nt][0] - mnA); psA += s_acc[nt][0];
                s_acc[nt][1] = __expf(s_acc[nt][1] - mnA); psA += s_acc[nt][1];
                s_acc[nt][2] = __expf(s_acc[nt][2] - mnB); psB += s_acc[nt][2];
                s_acc[nt][3] = __expf(s_acc[nt][3] - mnB); psB += s_acc[nt][3];
            }
            psA += __shfl_xor_sync(0xffffffffu, psA, 1);
            psA += __shfl_xor_sync(0xffffffffu, psA, 2);
            psB += __shfl_xor_sync(0xffffffffu, psB, 1);
            psB += __shfl_xor_sync(0xffffffffu, psB, 2);
            lA = lA * corrA + psA;  mA = mnA;
            lB = lB * corrB + psB;  mB = mnB;
            #pragma unroll
            for (int nt = 0; nt < 8; ++nt) {
                o[nt][0] *= corrA; o[nt][1] *= corrA;
                o[nt][2] *= corrB; o[nt][3] *= corrB;
            }

            #pragma unroll
            for (int kk = 0; kk < 4; ++kk) {
                int n0 = 2 * kk, n1 = 2 * kk + 1;
                uint32_t ph[4];
                ph[0] = f2h2(s_acc[n0][0], s_acc[n0][1]);
                ph[1] = f2h2(s_acc[n0][2], s_acc[n0][3]);
                ph[2] = f2h2(s_acc[n1][0], s_acc[n1][1]);
                ph[3] = f2h2(s_acc[n1][2], s_acc[n1][3]);
                uint32_t vh2[8][2];
                #pragma unroll
                for (int p = 0; p < 4; ++p) {
                    int r = p * 16 + ((lane >> 4) & 1) * 8 + (lane & 7);
                    int c = kk * 16 + ((lane >> 3) & 1) * 8;
                    uint32_t tmp[4];
                    ldsm4(tmp, sVh_ + r * APAD + c);
                    vh2[2*p][0] = tmp[0]; vh2[2*p][1] = tmp[1];
                    vh2[2*p+1][0] = tmp[2]; vh2[2*p+1][1] = tmp[3];
                }
                #pragma unroll
                for (int nt = 0; nt < 8; ++nt)
                    mma_f16(o[nt], ph, vh2[nt]);
            }
        }
    }

    float invA = 1.f / lA, invB = 1.f / lB;
    int rowA = qt * 128 + w * 16 + g;
    size_t baseA = ((size_t)(b * S_LEN + rowA)) * DMODEL + h * HDIM;
    size_t baseB = baseA + (size_t)8 * DMODEL;
    #pragma unroll
    for (int nt = 0; nt < 8; ++nt) {
        int c = nt * 8 + 2 * q;
        float a0 = o[nt][0] * invA, a1 = o[nt][1] * invA;
        float b0 = o[nt][2] * invB, b1 = o[nt][3] * invB;
        *(uint32_t*)(Ch + baseA + c) = f2h2(a0, a1);
        *(uint32_t*)(Ch + baseB + c) = f2h2(b0, b1);
    }
}

// ---------------------------------------------------------------------------
// Launcher
// ---------------------------------------------------------------------------
extern "C" void kernel_launch(void* const* d_in, const int* in_sizes, int n_in,
                              void* d_out, int out_size)
{
    const float* hs     = (const float*)d_in[0];
    const float* gamma  = (const float*)d_in[1];
    const float* beta   = (const float*)d_in[2];
    const float* qkv_w  = (const float*)d_in[3];
    const float* qkv_b  = (const float*)d_in[4];
    const float* proj_w = (const float*)d_in[5];
    const float* proj_b = (const float*)d_in[6];
    float* out = (float*)d_out;

    void *pqkv, *pxh, *pwqh, *pwph, *pch;
    void *pqh, *pkh, *pvh;
    cudaGetSymbolAddress(&pqkv, g_qkv);
    cudaGetSymbolAddress(&pxh,  g_xh);
    cudaGetSymbolAddress(&pwqh, g_wqh); cudaGetSymbolAddress(&pwph, g_wph);
    cudaGetSymbolAddress(&pch,  g_ch);
    cudaGetSymbolAddress(&pqh,  g_qhh);
    cudaGetSymbolAddress(&pkh,  g_khh); cudaGetSymbolAddress(&pvh,  g_vth);

    cudaFuncSetAttribute(mma_gemm_smem,
        cudaFuncAttributeMaxDynamicSharedMemorySize, GEMM_SMEM);
    cudaFuncSetAttribute(attn_mma_kernel,
        cudaFuncAttributeMaxDynamicSharedMemorySize, ATT_SMEM);

    // 1) LayerNorm -> fp16
    ln_split_kernel<<<ROWS, 256>>>(hs, gamma, beta, (unsigned short*)pxh);

    // weight conversions
    w_f16_kernel<<<(QKVD*DMODEL/4)/256, 256>>>(qkv_w,
        (unsigned short*)pwqh, QKVD*DMODEL/4);
    w_f16_kernel<<<(DMODEL*DMODEL/4)/256, 256>>>(proj_w,
        (unsigned short*)pwph, DMODEL*DMODEL/4);

    // 2) QKV GEMM (pure fp16)
    mma_gemm_smem<<<dim3(QKVD/128, ROWS/128), 128, GEMM_SMEM>>>(
        (unsigned short*)pxh, (unsigned short*)pwqh,
        qkv_b, (float*)pqkv, ROWS, QKVD, DMODEL);

    // 3) RoPE + relayout, V transpose
    rope_convert_kernel<<<(BATCH*S_LEN*NHEAD*32)/256, 256>>>((float*)pqkv,
        (unsigned short*)pqh, (unsigned short*)pkh);
    v_transpose_kernel<<<dim3(S_LEN/64, BH), 256>>>((float*)pqkv,
        (unsigned short*)pvh);

    // 4) Attention (pure fp16 inputs, f32 accum; writes fp16 ctx)
    attn_mma_kernel<<<dim3(S_LEN/128, BH), 256, ATT_SMEM>>>(
        (unsigned short*)pqh, (unsigned short*)pkh, (unsigned short*)pvh,
        (unsigned short*)pch);

    // 5) Output projection (pure fp16)
    mma_gemm_smem<<<dim3(DMODEL/128, ROWS/128), 128, GEMM_SMEM>>>(
        (unsigned short*)pch, (unsigned short*)pwph,
        proj_b, out, ROWS, DMODEL, DMODEL);
}

// round 11
// speedup vs baseline: 2.1710x; 1.0185x over previous
#include <cuda_runtime.h>
#include <cuda_fp16.h>
#include <math.h>
#include <stdint.h>

// Problem constants
#define BATCH   2
#define S_LEN   2048
#define DMODEL  1024
#define NHEAD   16
#define HDIM    64
#define QKVD    (3*DMODEL)     // 3072
#define ROWS    (BATCH*S_LEN)  // 4096
#define BH      (BATCH*NHEAD)  // 32

// Scratch (device globals). fp16 stored as ushort.
__device__ float g_qkv[ROWS * QKVD];                       // qkv fp32 (pre-rope)
__device__ unsigned short g_xh[ROWS * DMODEL];             // LN output
__device__ unsigned short g_wqh[QKVD * DMODEL];            // weights
__device__ unsigned short g_wph[DMODEL * DMODEL];
__device__ unsigned short g_ch[ROWS * DMODEL];             // ctx
__device__ unsigned short g_qhh[BH * S_LEN * HDIM];        // Q (post-rope, scaled*log2e)
__device__ unsigned short g_khh[BH * S_LEN * HDIM];        // K
__device__ unsigned short g_vth[BH * HDIM * S_LEN];        // V^T

// ---------------------------------------------------------------------------
// helpers
// ---------------------------------------------------------------------------
__device__ __forceinline__ uint32_t f2h2(float a, float b) {
    __half2 t = __floats2half2_rn(a, b);
    return *reinterpret_cast<uint32_t*>(&t);
}
__device__ __forceinline__ uint32_t sptr(const void* p) {
    return (uint32_t)__cvta_generic_to_shared(p);
}
__device__ __forceinline__ void cp16(void* dst, const void* src) {
    asm volatile("cp.async.cg.shared.global [%0], [%1], 16;\n"
                 :: "r"(sptr(dst)), "l"(src));
}
__device__ __forceinline__ void cp_commit() { asm volatile("cp.async.commit_group;\n"); }
__device__ __forceinline__ void cp_wait0()  { asm volatile("cp.async.wait_group 0;\n"); }
__device__ __forceinline__ void cp_wait1()  { asm volatile("cp.async.wait_group 1;\n"); }

__device__ __forceinline__ void ldsm4(uint32_t* r, const void* p) {
    asm volatile("ldmatrix.sync.aligned.m8n8.x4.shared.b16 {%0,%1,%2,%3}, [%4];\n"
                 : "=r"(r[0]), "=r"(r[1]), "=r"(r[2]), "=r"(r[3]) : "r"(sptr(p)));
}
// f16 inputs, f32 accumulate
__device__ __forceinline__ void mma_f16(float* c, const uint32_t* a, const uint32_t* b) {
    asm volatile(
        "mma.sync.aligned.m16n8k16.row.col.f32.f16.f16.f32 "
        "{%0,%1,%2,%3}, {%4,%5,%6,%7}, {%8,%9}, {%0,%1,%2,%3};\n"
        : "+f"(c[0]), "+f"(c[1]), "+f"(c[2]), "+f"(c[3])
        : "r"(a[0]), "r"(a[1]), "r"(a[2]), "r"(a[3]), "r"(b[0]), "r"(b[1]));
}

// ---------------------------------------------------------------------------
// 1) LayerNorm -> fp16 output
// ---------------------------------------------------------------------------
__global__ void __launch_bounds__(256) ln_split_kernel(
    const float* __restrict__ x, const float* __restrict__ gamma,
    const float* __restrict__ beta, unsigned short* __restrict__ yh)
{
    __shared__ float red_s[8], red_ss[8];
    __shared__ float sh_mean, sh_inv;
    int row = blockIdx.x;
    int tid = threadIdx.x;
    const float4* xr = (const float4*)(x + (size_t)row * DMODEL);
    float4 v = xr[tid];
    float s  = v.x + v.y + v.z + v.w;
    float ss = v.x*v.x + v.y*v.y + v.z*v.z + v.w*v.w;
    #pragma unroll
    for (int off = 16; off > 0; off >>= 1) {
        s  += __shfl_down_sync(0xffffffffu, s,  off);
        ss += __shfl_down_sync(0xffffffffu, ss, off);
    }
    int wid = tid >> 5, lane = tid & 31;
    if (lane == 0) { red_s[wid] = s; red_ss[wid] = ss; }
    __syncthreads();
    if (tid == 0) {
        float S = 0.f, SS = 0.f;
        #pragma unroll
        for (int i = 0; i < 8; ++i) { S += red_s[i]; SS += red_ss[i]; }
        float mean = S * (1.f / DMODEL);
        float var  = SS * (1.f / DMODEL) - mean * mean;
        sh_mean = mean;
        sh_inv  = rsqrtf(var + 1e-5f);
    }
    __syncthreads();
    float mean = sh_mean, inv = sh_inv;
    float4 gv = ((const float4*)gamma)[tid];
    float4 bv = ((const float4*)beta)[tid];
    float o0 = (v.x - mean) * inv * gv.x + bv.x;
    float o1 = (v.y - mean) * inv * gv.y + bv.y;
    float o2 = (v.z - mean) * inv * gv.z + bv.z;
    float o3 = (v.w - mean) * inv * gv.w + bv.w;
    uint2 hv = make_uint2(f2h2(o0, o1), f2h2(o2, o3));
    *(uint2*)(yh + (size_t)row * DMODEL + tid * 4) = hv;
}

// ---------------------------------------------------------------------------
// weights: fp32 -> fp16, 4 elements/thread
// ---------------------------------------------------------------------------
__global__ void __launch_bounds__(256) w_f16_kernel(
    const float* __restrict__ x, unsigned short* __restrict__ hi, int n4)
{
    int i = blockIdx.x * 256 + threadIdx.x;
    if (i >= n4) return;
    float4 v = ((const float4*)x)[i];
    uint2 hv = make_uint2(f2h2(v.x, v.y), f2h2(v.z, v.w));
    *(uint2*)(hi + (size_t)i * 4) = hv;
}

// ---------------------------------------------------------------------------
// 2) Pure-fp16 smem-staged double-buffered GEMM: C = A@B^T + bias.
//    Block 128x128, BK=32, 4 warps (2x2), warp tile 64x64.
// ---------------------------------------------------------------------------
#define GPAD 40
#define GTILE (128 * GPAD)            // ushorts per tile
#define GSTAGE (2 * GTILE)            // Ah,Bh
#define GEMM_SMEM (2 * GSTAGE * 2)    // bytes = 40960

__global__ void __launch_bounds__(128) mma_gemm_smem(
    const unsigned short* __restrict__ Ahg, const unsigned short* __restrict__ Bhg,
    const float* __restrict__ bias, float* __restrict__ C,
    int M, int N, int K)
{
    extern __shared__ unsigned short smg[];
    int t = threadIdx.x;
    int wid = t >> 5, lane = t & 31;
    int wm = wid >> 1, wn = wid & 1;
    int g = lane >> 2, q = lane & 3;
    int mb = blockIdx.y * 128, nb = blockIdx.x * 128;

    float acc[4][8][4];
    #pragma unroll
    for (int mt = 0; mt < 4; ++mt)
        #pragma unroll
        for (int nt = 0; nt < 8; ++nt)
            #pragma unroll
            for (int e = 0; e < 4; ++e) acc[mt][nt][e] = 0.f;

    const int NKB = K >> 5;

    auto load_stage = [&](int st, int k0) {
        unsigned short* base = smg + st * GSTAGE;
        #pragma unroll
        for (int i = 0; i < 4; ++i) {
            int ch = t + i * 128;          // 0..511
            int row = ch >> 2, c = ch & 3;
            int soff = row * GPAD + c * 8;
            size_t goffA = (size_t)(mb + row) * K + k0 + c * 8;
            size_t goffB = (size_t)(nb + row) * K + k0 + c * 8;
            cp16(base + soff,         Ahg + goffA);
            cp16(base + GTILE + soff, Bhg + goffB);
        }
        cp_commit();
    };

    load_stage(0, 0);

    for (int kb = 0; kb < NKB; ++kb) {
        cp_wait0();
        __syncthreads();
        if (kb + 1 < NKB) load_stage((kb + 1) & 1, (kb + 1) << 5);

        unsigned short* base = smg + (kb & 1) * GSTAGE;
        unsigned short* sAh = base;
        unsigned short* sBh = base + GTILE;

        #pragma unroll
        for (int kk = 0; kk < 2; ++kk) {
            uint32_t ah[4][4];
            #pragma unroll
            for (int mt = 0; mt < 4; ++mt) {
                int r = wm * 64 + mt * 16 + (lane & 15);
                int c = kk * 16 + (lane >> 4) * 8;
                ldsm4(ah[mt], sAh + r * GPAD + c);
            }
            uint32_t bh2[8][2];
            #pragma unroll
            for (int p = 0; p < 4; ++p) {
                int r = wn * 64 + p * 16 + ((lane >> 4) & 1) * 8 + (lane & 7);
                int c = kk * 16 + ((lane >> 3) & 1) * 8;
                uint32_t tmp[4];
                ldsm4(tmp, sBh + r * GPAD + c);
                bh2[2*p][0] = tmp[0]; bh2[2*p][1] = tmp[1];
                bh2[2*p+1][0] = tmp[2]; bh2[2*p+1][1] = tmp[3];
            }
            #pragma unroll
            for (int mt = 0; mt < 4; ++mt)
                #pragma unroll
                for (int nt = 0; nt < 8; ++nt)
                    mma_f16(acc[mt][nt], ah[mt], bh2[nt]);
        }
    }

    #pragma unroll
    for (int mt = 0; mt < 4; ++mt) {
        #pragma unroll
        for (int nt = 0; nt < 8; ++nt) {
            int r = mb + wm * 64 + mt * 16 + g;
            int c = nb + wn * 64 + nt * 8 + q * 2;
            float b0 = bias[c], b1 = bias[c + 1];
            float2 v0; v0.x = acc[mt][nt][0] + b0; v0.y = acc[mt][nt][1] + b1;
            float2 v1; v1.x = acc[mt][nt][2] + b0; v1.y = acc[mt][nt][3] + b1;
            *(float2*)(C + (size_t)r * N + c)       = v0;
            *(float2*)(C + (size_t)(r + 8) * N + c) = v1;
        }
    }
}

// ---------------------------------------------------------------------------
// 3) RoPE + head-major relayout. Q pre-scaled by 0.125*log2(e) so attention
//    logits are in log2 units (softmax is scale-invariant; exp -> exp2f).
// ---------------------------------------------------------------------------
__global__ void __launch_bounds__(256) rope_convert_kernel(
    const float* __restrict__ qkv,
    unsigned short* __restrict__ Qh, unsigned short* __restrict__ Kh)
{
    int idx = blockIdx.x * 256 + threadIdx.x;   // B*S*H*32
    int i  = idx & 31;
    int h  = (idx >> 5) & 15;
    int sb = idx >> 9;
    int s  = sb & (S_LEN - 1);
    int b  = sb >> 11;
    const double C = 0.28782844202394213;       // ln(10000)/32
    double ang = (double)s * exp(-C * (double)i);
    double n   = rint(ang * 0.15915494309189535); // 1/(2*pi)
    float ar   = (float)(ang - n * 6.283185307179586);
    float c  = cosf(ar);
    float sn = sinf(ar);
    const float QSCALE = 0.125f * 1.4426950408889634f;  // 1/sqrt(64) * log2(e)

    size_t base = (size_t)sb * QKVD + h * (3 * HDIM);
    float q1 = qkv[base + i],      q2 = qkv[base + 32 + i];
    float k1 = qkv[base + 64 + i], k2 = qkv[base + 96 + i];
    float qo1 = (q1 * c - q2 * sn) * QSCALE;
    float qo2 = (q2 * c + q1 * sn) * QSCALE;
    float ko1 = k1 * c - k2 * sn;
    float ko2 = k2 * c + k1 * sn;

    size_t dst = ((size_t)(b * NHEAD + h) * S_LEN + s) * HDIM;
    Qh[dst + i]      = __half_as_ushort(__float2half_rn(qo1));
    Qh[dst + 32 + i] = __half_as_ushort(__float2half_rn(qo2));
    Kh[dst + i]      = __half_as_ushort(__float2half_rn(ko1));
    Kh[dst + 32 + i] = __half_as_ushort(__float2half_rn(ko2));
}

// ---------------------------------------------------------------------------
// 3b) V transpose: Vt[bh][d][s] fp16.
// ---------------------------------------------------------------------------
__global__ void __launch_bounds__(256) v_transpose_kernel(
    const float* __restrict__ qkv, unsigned short* __restrict__ Vth)
{
    __shared__ float tile[64][67];
    int st = blockIdx.x, bh = blockIdx.y;
    int b = bh >> 4, h = bh & 15;
    int t = threadIdx.x;
    #pragma unroll
    for (int it = 0; it < 4; ++it) {
        int id = t + it * 256;            // 0..1023
        int sl = id >> 4, f4 = id & 15;
        int sb = b * S_LEN + st * 64 + sl;
        float4 v = *(const float4*)(qkv + (size_t)sb * QKVD + h * 192 + 128 + f4 * 4);
        tile[sl][f4*4+0] = v.x; tile[sl][f4*4+1] = v.y;
        tile[sl][f4*4+2] = v.z; tile[sl][f4*4+3] = v.w;
    }
    __syncthreads();
    #pragma unroll
    for (int it = 0; it < 16; ++it) {
        int d  = it * 4 + (t >> 6);
        int sl = t & 63;
        float v = tile[sl][d];
        size_t dst = ((size_t)bh * HDIM + d) * S_LEN + st * 64 + sl;
        Vth[dst] = __half_as_ushort(__float2half_rn(v));
    }
}

// ---------------------------------------------------------------------------
// 4) Pure-fp16 flash attention, KV tile 128 (halved iteration fixed costs),
//    exp2-domain softmax, double-buffered K/V, qt reversed.
// ---------------------------------------------------------------------------
#define APAD 72            // K/Q row pad (64+8 halves)
#define VPAD 136           // V^T row pad (128+8 halves)
#define AQT (128 * APAD)   // Q tile ushorts
#define KT  (128 * APAD)   // K tile: 128 rows x 64 cols
#define VT  (64 * VPAD)    // V^T tile: 64 rows x 128 cols
#define AST (KT + VT)      // one stage
#define ATT_SMEM ((AQT + 2 * AST) * 2)   // 90112 bytes

__global__ void __launch_bounds__(256) attn_mma_kernel(
    const unsigned short* __restrict__ Qh,
    const unsigned short* __restrict__ Kh, const unsigned short* __restrict__ Vth,
    unsigned short* __restrict__ Ch)
{
    extern __shared__ unsigned short sma[];
    unsigned short* sQh = sma;
    unsigned short* sKV = sma + AQT;   // 2 stages of [K|V]

    int qt = gridDim.x - 1 - blockIdx.x;   // biggest workloads launch first
    int bh = blockIdx.y;
    int b = bh >> 4, h = bh & 15;
    int t = threadIdx.x;
    int w = t >> 5, lane = t & 31;
    int g = lane >> 2, q = lane & 3;

    auto load_kv = [&](int st, int kt) {
        unsigned short* sg = sKV + st * AST;
        size_t kbase = ((size_t)bh * S_LEN + kt * 128) * HDIM;
        #pragma unroll
        for (int i = 0; i < 4; ++i) {          // K: 128 rows x 8 chunks
            int ch = t + i * 256;              // 0..1023
            int row = ch >> 3, c = ch & 7;
            cp16(sg + row * APAD + c * 8, Kh + kbase + row * 64 + c * 8);
        }
        #pragma unroll
        for (int i = 0; i < 4; ++i) {          // V^T: 64 rows x 16 chunks
            int ch = t + i * 256;              // 0..1023
            int row = ch >> 4, c = ch & 15;
            size_t vsrc = ((size_t)bh * HDIM + row) * S_LEN + kt * 128 + c * 8;
            cp16(sg + KT + row * VPAD + c * 8, Vth + vsrc);
        }
        cp_commit();
    };

    // prologue: stage Q, prefetch kv tile 0
    size_t qbase = ((size_t)bh * S_LEN + qt * 128) * HDIM;
    #pragma unroll
    for (int i = 0; i < 4; ++i) {
        int ch = t + i * 256;                  // 0..1023
        int row = ch >> 3, c = ch & 7;
        cp16(sQh + row * APAD + c * 8, Qh + qbase + row * 64 + c * 8);
    }
    cp_commit();
    load_kv(0, 0);
    cp_wait1();
    __syncthreads();

    uint32_t qfh[4][4];
    #pragma unroll
    for (int kk = 0; kk < 4; ++kk) {
        int r = w * 16 + (lane & 15);
        int c = kk * 16 + (lane >> 4) * 8;
        ldsm4(qfh[kk], sQh + r * APAD + c);
    }

    float o[8][4];
    #pragma unroll
    for (int nt = 0; nt < 8; ++nt)
        #pragma unroll
        for (int e = 0; e < 4; ++e) o[nt][e] = 0.f;
    float mA = -1e30f, mB = -1e30f, lA = 0.f, lB = 0.f;

    int qrA = qt * 128 + w * 16 + g;
    int nk = qt + 1;

    for (int kt = 0; kt < nk; ++kt) {
        cp_wait0();
        __syncthreads();
        if (kt + 1 < nk) load_kv((kt + 1) & 1, kt + 1);

        unsigned short* sg  = sKV + (kt & 1) * AST;
        unsigned short* sK_ = sg;
        unsigned short* sV_ = sg + KT;

        // S = Q K^T  (logits in log2 units)
        float s_acc[16][4];
        #pragma unroll
        for (int nt = 0; nt < 16; ++nt)
            #pragma unroll
            for (int e = 0; e < 4; ++e) s_acc[nt][e] = 0.f;

        #pragma unroll
        for (int kk = 0; kk < 4; ++kk) {
            uint32_t bh2[16][2];
            #pragma unroll
            for (int p = 0; p < 8; ++p) {
                int r = p * 16 + ((lane >> 4) & 1) * 8 + (lane & 7);
                int c = kk * 16 + ((lane >> 3) & 1) * 8;
                uint32_t tmp[4];
                ldsm4(tmp, sK_ + r * APAD + c);
                bh2[2*p][0] = tmp[0]; bh2[2*p][1] = tmp[1];
                bh2[2*p+1][0] = tmp[2]; bh2[2*p+1][1] = tmp[3];
            }
            #pragma unroll
            for (int nt = 0; nt < 16; ++nt)
                mma_f16(s_acc[nt], qfh[kk], bh2[nt]);
        }

        // causal mask
        int kb0 = kt * 128;
        if (kb0 + 127 > qrA) {
            #pragma unroll
            for (int nt = 0; nt < 16; ++nt) {
                int colb = kb0 + nt * 8 + 2 * q;
                if (colb     > qrA)     s_acc[nt][0] = -1e30f;
                if (colb + 1 > qrA)     s_acc[nt][1] = -1e30f;
                if (colb     > qrA + 8) s_acc[nt][2] = -1e30f;
                if (colb + 1 > qrA + 8) s_acc[nt][3] = -1e30f;
            }
        }

        // online softmax (base-2)
        float mxA = -1e30f, mxB = -1e30f;
        #pragma unroll
        for (int nt = 0; nt < 16; ++nt) {
            mxA = fmaxf(mxA, fmaxf(s_acc[nt][0], s_acc[nt][1]));
            mxB = fmaxf(mxB, fmaxf(s_acc[nt][2], s_acc[nt][3]));
        }
        mxA = fmaxf(mxA, __shfl_xor_sync(0xffffffffu, mxA, 1));
        mxA = fmaxf(mxA, __shfl_xor_sync(0xffffffffu, mxA, 2));
        mxB = fmaxf(mxB, __shfl_xor_sync(0xffffffffu, mxB, 1));
        mxB = fmaxf(mxB, __shfl_xor_sync(0xffffffffu, mxB, 2));
        float mnA = fmaxf(mA, mxA), mnB = fmaxf(mB, mxB);
        float corrA = exp2f(mA - mnA), corrB = exp2f(mB - mnB);
        float psA = 0.f, psB = 0.f;
        #pragma unroll
        for (int nt = 0; nt < 16; ++nt) {
            s_acc[nt][0] = exp2f(s_acc[nt][0] - mnA); psA += s_acc[nt][0];
            s_acc[nt][1] = exp2f(s_acc[nt][1] - mnA); psA += s_acc[nt][1];
            s_acc[nt][2] = exp2f(s_acc[nt][2] - mnB); psB += s_acc[nt][2];
            s_acc[nt][3] = exp2f(s_acc[nt][3] - mnB); psB += s_acc[nt][3];
        }
        psA += __shfl_xor_sync(0xffffffffu, psA, 1);
        psA += __shfl_xor_sync(0xffffffffu, psA, 2);
        psB += __shfl_xor_sync(0xffffffffu, psB, 1);
        psB += __shfl_xor_sync(0xffffffffu, psB, 2);
        lA = lA * corrA + psA;  mA = mnA;
        lB = lB * corrB + psB;  mB = mnB;
        #pragma unroll
        for (int nt = 0; nt < 8; ++nt) {
            o[nt][0] *= corrA; o[nt][1] *= corrA;
            o[nt][2] *= corrB; o[nt][3] *= corrB;
        }

        // O += P V  (k dim = 128 s-positions, 8 chunks)
        #pragma unroll
        for (int kk = 0; kk < 8; ++kk) {
            int n0 = 2 * kk, n1 = 2 * kk + 1;
            uint32_t ph[4];
            ph[0] = f2h2(s_acc[n0][0], s_acc[n0][1]);
            ph[1] = f2h2(s_acc[n0][2], s_acc[n0][3]);
            ph[2] = f2h2(s_acc[n1][0], s_acc[n1][1]);
            ph[3] = f2h2(s_acc[n1][2], s_acc[n1][3]);
            uint32_t vh2[8][2];
            #pragma unroll
            for (int p = 0; p < 4; ++p) {
                int r = p * 16 + ((lane >> 4) & 1) * 8 + (lane & 7);
                int c = kk * 16 + ((lane >> 3) & 1) * 8;
                uint32_t tmp[4];
                ldsm4(tmp, sV_ + r * VPAD + c);
                vh2[2*p][0] = tmp[0]; vh2[2*p][1] = tmp[1];
                vh2[2*p+1][0] = tmp[2]; vh2[2*p+1][1] = tmp[3];
            }
            #pragma unroll
            for (int nt = 0; nt < 8; ++nt)
                mma_f16(o[nt], ph, vh2[nt]);
        }
    }

    float invA = 1.f / lA, invB = 1.f / lB;
    int rowA = qt * 128 + w * 16 + g;
    size_t baseA = ((size_t)(b * S_LEN + rowA)) * DMODEL + h * HDIM;
    size_t baseB = baseA + (size_t)8 * DMODEL;
    #pragma unroll
    for (int nt = 0; nt < 8; ++nt) {
        int c = nt * 8 + 2 * q;
        float a0 = o[nt][0] * invA, a1 = o[nt][1] * invA;
        float b0 = o[nt][2] * invB, b1 = o[nt][3] * invB;
        *(uint32_t*)(Ch + baseA + c) = f2h2(a0, a1);
        *(uint32_t*)(Ch + baseB + c) = f2h2(b0, b1);
    }
}

// ---------------------------------------------------------------------------
// Launcher
// ---------------------------------------------------------------------------
extern "C" void kernel_launch(void* const* d_in, const int* in_sizes, int n_in,
                              void* d_out, int out_size)
{
    const float* hs     = (const float*)d_in[0];
    const float* gamma  = (const float*)d_in[1];
    const float* beta   = (const float*)d_in[2];
    const float* qkv_w  = (const float*)d_in[3];
    const float* qkv_b  = (const float*)d_in[4];
    const float* proj_w = (const float*)d_in[5];
    const float* proj_b = (const float*)d_in[6];
    float* out = (float*)d_out;

    void *pqkv, *pxh, *pwqh, *pwph, *pch;
    void *pqh, *pkh, *pvh;
    cudaGetSymbolAddress(&pqkv, g_qkv);
    cudaGetSymbolAddress(&pxh,  g_xh);
    cudaGetSymbolAddress(&pwqh, g_wqh); cudaGetSymbolAddress(&pwph, g_wph);
    cudaGetSymbolAddress(&pch,  g_ch);
    cudaGetSymbolAddress(&pqh,  g_qhh);
    cudaGetSymbolAddress(&pkh,  g_khh); cudaGetSymbolAddress(&pvh,  g_vth);

    cudaFuncSetAttribute(mma_gemm_smem,
        cudaFuncAttributeMaxDynamicSharedMemorySize, GEMM_SMEM);
    cudaFuncSetAttribute(attn_mma_kernel,
        cudaFuncAttributeMaxDynamicSharedMemorySize, ATT_SMEM);

    // 1) LayerNorm -> fp16
    ln_split_kernel<<<ROWS, 256>>>(hs, gamma, beta, (unsigned short*)pxh);

    // weight conversions
    w_f16_kernel<<<(QKVD*DMODEL/4)/256, 256>>>(qkv_w,
        (unsigned short*)pwqh, QKVD*DMODEL/4);
    w_f16_kernel<<<(DMODEL*DMODEL/4)/256, 256>>>(proj_w,
        (unsigned short*)pwph, DMODEL*DMODEL/4);

    // 2) QKV GEMM (pure fp16)
    mma_gemm_smem<<<dim3(QKVD/128, ROWS/128), 128, GEMM_SMEM>>>(
        (unsigned short*)pxh, (unsigned short*)pwqh,
        qkv_b, (float*)pqkv, ROWS, QKVD, DMODEL);

    // 3) RoPE + relayout, V transpose
    rope_convert_kernel<<<(BATCH*S_LEN*NHEAD*32)/256, 256>>>((float*)pqkv,
        (unsigned short*)pqh, (unsigned short*)pkh);
    v_transpose_kernel<<<dim3(S_LEN/64, BH), 256>>>((float*)pqkv,
        (unsigned short*)pvh);

    // 4) Attention (pure fp16, KV tile 128, exp2 softmax)
    attn_mma_kernel<<<dim3(S_LEN/128, BH), 256, ATT_SMEM>>>(
        (unsigned short*)pqh, (unsigned short*)pkh, (unsigned short*)pvh,
        (unsigned short*)pch);

    // 5) Output projection (pure fp16)
    mma_gemm_smem<<<dim3(DMODEL/128, ROWS/128), 128, GEMM_SMEM>>>(
        (unsigned short*)pch, (unsigned short*)pwph,
        proj_b, out, ROWS, DMODEL, DMODEL);
}

// round 13
// speedup vs baseline: 2.2146x; 1.0201x over previous
#include <cuda_runtime.h>
#include <cuda_fp16.h>
#include <math.h>
#include <stdint.h>

// Problem constants
#define BATCH   2
#define S_LEN   2048
#define DMODEL  1024
#define NHEAD   16
#define HDIM    64
#define QKVD    (3*DMODEL)     // 3072
#define ROWS    (BATCH*S_LEN)  // 4096
#define BH      (BATCH*NHEAD)  // 32

// Scratch (device globals). fp16 stored as ushort.
__device__ float g_qkv[ROWS * QKVD];                       // qkv fp32 (pre-rope)
__device__ unsigned short g_xh[ROWS * DMODEL];             // LN output
__device__ unsigned short g_wqh[QKVD * DMODEL];            // weights
__device__ unsigned short g_wph[DMODEL * DMODEL];
__device__ unsigned short g_ch[ROWS * DMODEL];             // ctx
__device__ unsigned short g_qhh[BH * S_LEN * HDIM];        // Q (post-rope, scaled*log2e)
__device__ unsigned short g_khh[BH * S_LEN * HDIM];        // K
__device__ unsigned short g_vth[BH * HDIM * S_LEN];        // V^T

// ---------------------------------------------------------------------------
// helpers
// ---------------------------------------------------------------------------
__device__ __forceinline__ uint32_t f2h2(float a, float b) {
    __half2 t = __floats2half2_rn(a, b);
    return *reinterpret_cast<uint32_t*>(&t);
}
__device__ __forceinline__ uint32_t ex2_h2(uint32_t x) {
    uint32_t r;
    asm("ex2.approx.f16x2 %0, %1;" : "=r"(r) : "r"(x));
    return r;
}
__device__ __forceinline__ uint32_t sptr(const void* p) {
    return (uint32_t)__cvta_generic_to_shared(p);
}
__device__ __forceinline__ void cp16(void* dst, const void* src) {
    asm volatile("cp.async.cg.shared.global [%0], [%1], 16;\n"
                 :: "r"(sptr(dst)), "l"(src));
}
__device__ __forceinline__ void cp_commit() { asm volatile("cp.async.commit_group;\n"); }
__device__ __forceinline__ void cp_wait0()  { asm volatile("cp.async.wait_group 0;\n"); }
__device__ __forceinline__ void cp_wait1()  { asm volatile("cp.async.wait_group 1;\n"); }

__device__ __forceinline__ void ldsm4(uint32_t* r, const void* p) {
    asm volatile("ldmatrix.sync.aligned.m8n8.x4.shared.b16 {%0,%1,%2,%3}, [%4];\n"
                 : "=r"(r[0]), "=r"(r[1]), "=r"(r[2]), "=r"(r[3]) : "r"(sptr(p)));
}
// f16 inputs, f32 accumulate
__device__ __forceinline__ void mma_f16(float* c, const uint32_t* a, const uint32_t* b) {
    asm volatile(
        "mma.sync.aligned.m16n8k16.row.col.f32.f16.f16.f32 "
        "{%0,%1,%2,%3}, {%4,%5,%6,%7}, {%8,%9}, {%0,%1,%2,%3};\n"
        : "+f"(c[0]), "+f"(c[1]), "+f"(c[2]), "+f"(c[3])
        : "r"(a[0]), "r"(a[1]), "r"(a[2]), "r"(a[3]), "r"(b[0]), "r"(b[1]));
}

// ---------------------------------------------------------------------------
// 1) LayerNorm -> fp16 output
// ---------------------------------------------------------------------------
__global__ void __launch_bounds__(256) ln_split_kernel(
    const float* __restrict__ x, const float* __restrict__ gamma,
    const float* __restrict__ beta, unsigned short* __restrict__ yh)
{
    __shared__ float red_s[8], red_ss[8];
    __shared__ float sh_mean, sh_inv;
    int row = blockIdx.x;
    int tid = threadIdx.x;
    const float4* xr = (const float4*)(x + (size_t)row * DMODEL);
    float4 v = xr[tid];
    float s  = v.x + v.y + v.z + v.w;
    float ss = v.x*v.x + v.y*v.y + v.z*v.z + v.w*v.w;
    #pragma unroll
    for (int off = 16; off > 0; off >>= 1) {
        s  += __shfl_down_sync(0xffffffffu, s,  off);
        ss += __shfl_down_sync(0xffffffffu, ss, off);
    }
    int wid = tid >> 5, lane = tid & 31;
    if (lane == 0) { red_s[wid] = s; red_ss[wid] = ss; }
    __syncthreads();
    if (tid == 0) {
        float S = 0.f, SS = 0.f;
        #pragma unroll
        for (int i = 0; i < 8; ++i) { S += red_s[i]; SS += red_ss[i]; }
        float mean = S * (1.f / DMODEL);
        float var  = SS * (1.f / DMODEL) - mean * mean;
        sh_mean = mean;
        sh_inv  = rsqrtf(var + 1e-5f);
    }
    __syncthreads();
    float mean = sh_mean, inv = sh_inv;
    float4 gv = ((const float4*)gamma)[tid];
    float4 bv = ((const float4*)beta)[tid];
    float o0 = (v.x - mean) * inv * gv.x + bv.x;
    float o1 = (v.y - mean) * inv * gv.y + bv.y;
    float o2 = (v.z - mean) * inv * gv.z + bv.z;
    float o3 = (v.w - mean) * inv * gv.w + bv.w;
    uint2 hv = make_uint2(f2h2(o0, o1), f2h2(o2, o3));
    *(uint2*)(yh + (size_t)row * DMODEL + tid * 4) = hv;
}

// ---------------------------------------------------------------------------
// weights: fp32 -> fp16, 4 elements/thread
// ---------------------------------------------------------------------------
__global__ void __launch_bounds__(256) w_f16_kernel(
    const float* __restrict__ x, unsigned short* __restrict__ hi, int n4)
{
    int i = blockIdx.x * 256 + threadIdx.x;
    if (i >= n4) return;
    float4 v = ((const float4*)x)[i];
    uint2 hv = make_uint2(f2h2(v.x, v.y), f2h2(v.z, v.w));
    *(uint2*)(hi + (size_t)i * 4) = hv;
}

// ---------------------------------------------------------------------------
// 2) Pure-fp16 smem-staged double-buffered GEMM: C = A@B^T + bias.
//    Block 128x128, BK=32, 4 warps (2x2), warp tile 64x64.
// ---------------------------------------------------------------------------
#define GPAD 40
#define GTILE (128 * GPAD)            // ushorts per tile
#define GSTAGE (2 * GTILE)            // Ah,Bh
#define GEMM_SMEM (2 * GSTAGE * 2)    // bytes = 40960

__global__ void __launch_bounds__(128) mma_gemm_smem(
    const unsigned short* __restrict__ Ahg, const unsigned short* __restrict__ Bhg,
    const float* __restrict__ bias, float* __restrict__ C,
    int M, int N, int K)
{
    extern __shared__ unsigned short smg[];
    int t = threadIdx.x;
    int wid = t >> 5, lane = t & 31;
    int wm = wid >> 1, wn = wid & 1;
    int g = lane >> 2, q = lane & 3;
    int mb = blockIdx.y * 128, nb = blockIdx.x * 128;

    float acc[4][8][4];
    #pragma unroll
    for (int mt = 0; mt < 4; ++mt)
        #pragma unroll
        for (int nt = 0; nt < 8; ++nt)
            #pragma unroll
            for (int e = 0; e < 4; ++e) acc[mt][nt][e] = 0.f;

    const int NKB = K >> 5;

    auto load_stage = [&](int st, int k0) {
        unsigned short* base = smg + st * GSTAGE;
        #pragma unroll
        for (int i = 0; i < 4; ++i) {
            int ch = t + i * 128;          // 0..511
            int row = ch >> 2, c = ch & 3;
            int soff = row * GPAD + c * 8;
            size_t goffA = (size_t)(mb + row) * K + k0 + c * 8;
            size_t goffB = (size_t)(nb + row) * K + k0 + c * 8;
            cp16(base + soff,         Ahg + goffA);
            cp16(base + GTILE + soff, Bhg + goffB);
        }
        cp_commit();
    };

    load_stage(0, 0);

    for (int kb = 0; kb < NKB; ++kb) {
        cp_wait0();
        __syncthreads();
        if (kb + 1 < NKB) load_stage((kb + 1) & 1, (kb + 1) << 5);

        unsigned short* base = smg + (kb & 1) * GSTAGE;
        unsigned short* sAh = base;
        unsigned short* sBh = base + GTILE;

        #pragma unroll
        for (int kk = 0; kk < 2; ++kk) {
            uint32_t ah[4][4];
            #pragma unroll
            for (int mt = 0; mt < 4; ++mt) {
                int r = wm * 64 + mt * 16 + (lane & 15);
                int c = kk * 16 + (lane >> 4) * 8;
                ldsm4(ah[mt], sAh + r * GPAD + c);
            }
            uint32_t bh2[8][2];
            #pragma unroll
            for (int p = 0; p < 4; ++p) {
                int r = wn * 64 + p * 16 + ((lane >> 4) & 1) * 8 + (lane & 7);
                int c = kk * 16 + ((lane >> 3) & 1) * 8;
                uint32_t tmp[4];
                ldsm4(tmp, sBh + r * GPAD + c);
                bh2[2*p][0] = tmp[0]; bh2[2*p][1] = tmp[1];
                bh2[2*p+1][0] = tmp[2]; bh2[2*p+1][1] = tmp[3];
            }
            #pragma unroll
            for (int mt = 0; mt < 4; ++mt)
                #pragma unroll
                for (int nt = 0; nt < 8; ++nt)
                    mma_f16(acc[mt][nt], ah[mt], bh2[nt]);
        }
    }

    #pragma unroll
    for (int mt = 0; mt < 4; ++mt) {
        #pragma unroll
        for (int nt = 0; nt < 8; ++nt) {
            int r = mb + wm * 64 + mt * 16 + g;
            int c = nb + wn * 64 + nt * 8 + q * 2;
            float b0 = bias[c], b1 = bias[c + 1];
            float2 v0; v0.x = acc[mt][nt][0] + b0; v0.y = acc[mt][nt][1] + b1;
            float2 v1; v1.x = acc[mt][nt][2] + b0; v1.y = acc[mt][nt][3] + b1;
            *(float2*)(C + (size_t)r * N + c)       = v0;
            *(float2*)(C + (size_t)(r + 8) * N + c) = v1;
        }
    }
}

// ---------------------------------------------------------------------------
// 3) RoPE + head-major relayout. Q pre-scaled by 0.125*log2(e) so attention
//    logits are in log2 units (softmax scale-invariant; exp -> exp2).
// ---------------------------------------------------------------------------
__global__ void __launch_bounds__(256) rope_convert_kernel(
    const float* __restrict__ qkv,
    unsigned short* __restrict__ Qh, unsigned short* __restrict__ Kh)
{
    int idx = blockIdx.x * 256 + threadIdx.x;   // B*S*H*32
    int i  = idx & 31;
    int h  = (idx >> 5) & 15;
    int sb = idx >> 9;
    int s  = sb & (S_LEN - 1);
    int b  = sb >> 11;
    const double C = 0.28782844202394213;       // ln(10000)/32
    double ang = (double)s * exp(-C * (double)i);
    double n   = rint(ang * 0.15915494309189535); // 1/(2*pi)
    float ar   = (float)(ang - n * 6.283185307179586);
    float c  = cosf(ar);
    float sn = sinf(ar);
    const float QSCALE = 0.125f * 1.4426950408889634f;  // 1/sqrt(64) * log2(e)

    size_t base = (size_t)sb * QKVD + h * (3 * HDIM);
    float q1 = qkv[base + i],      q2 = qkv[base + 32 + i];
    float k1 = qkv[base + 64 + i], k2 = qkv[base + 96 + i];
    float qo1 = (q1 * c - q2 * sn) * QSCALE;
    float qo2 = (q2 * c + q1 * sn) * QSCALE;
    float ko1 = k1 * c - k2 * sn;
    float ko2 = k2 * c + k1 * sn;

    size_t dst = ((size_t)(b * NHEAD + h) * S_LEN + s) * HDIM;
    Qh[dst + i]      = __half_as_ushort(__float2half_rn(qo1));
    Qh[dst + 32 + i] = __half_as_ushort(__float2half_rn(qo2));
    Kh[dst + i]      = __half_as_ushort(__float2half_rn(ko1));
    Kh[dst + 32 + i] = __half_as_ushort(__float2half_rn(ko2));
}

// ---------------------------------------------------------------------------
// 3b) V transpose: Vt[bh][d][s] fp16.
// ---------------------------------------------------------------------------
__global__ void __launch_bounds__(256) v_transpose_kernel(
    const float* __restrict__ qkv, unsigned short* __restrict__ Vth)
{
    __shared__ float tile[64][67];
    int st = blockIdx.x, bh = blockIdx.y;
    int b = bh >> 4, h = bh & 15;
    int t = threadIdx.x;
    #pragma unroll
    for (int it = 0; it < 4; ++it) {
        int id = t + it * 256;            // 0..1023
        int sl = id >> 4, f4 = id & 15;
        int sb = b * S_LEN + st * 64 + sl;
        float4 v = *(const float4*)(qkv + (size_t)sb * QKVD + h * 192 + 128 + f4 * 4);
        tile[sl][f4*4+0] = v.x; tile[sl][f4*4+1] = v.y;
        tile[sl][f4*4+2] = v.z; tile[sl][f4*4+3] = v.w;
    }
    __syncthreads();
    #pragma unroll
    for (int it = 0; it < 16; ++it) {
        int d  = it * 4 + (t >> 6);
        int sl = t & 63;
        float v = tile[sl][d];
        size_t dst = ((size_t)bh * HDIM + d) * S_LEN + st * 64 + sl;
        Vth[dst] = __half_as_ushort(__float2half_rn(v));
    }
}

// ---------------------------------------------------------------------------
// 4) Pure-fp16 flash attention, KV tile 128, f16x2 exp2 (2 scores/MUFU),
//    row-sum l via ones-rows 64..71 appended to V^T (every column of the
//    nt=8 output block computes l -> valid for all quad lanes q).
// ---------------------------------------------------------------------------
#define APAD 72            // K/Q row pad (64+8 halves)
#define VPAD 136           // V^T row pad (128+8 halves)
#define VROWS 80           // 64 d-rows + ones rows 64..71 + zero rows 72..79
#define AQT (128 * APAD)   // Q tile ushorts
#define KT  (128 * APAD)   // K tile: 128 rows x 64 cols
#define VT  (VROWS * VPAD) // V^T tile
#define AST (KT + VT)      // one stage
#define ATT_SMEM ((AQT + 2 * AST) * 2)

__global__ void __launch_bounds__(256) attn_mma_kernel(
    const unsigned short* __restrict__ Qh,
    const unsigned short* __restrict__ Kh, const unsigned short* __restrict__ Vth,
    unsigned short* __restrict__ Ch)
{
    extern __shared__ unsigned short sma[];
    unsigned short* sQh = sma;
    unsigned short* sKV = sma + AQT;   // 2 stages of [K|V]

    int qt = gridDim.x - 1 - blockIdx.x;   // biggest workloads launch first
    int bh = blockIdx.y;
    int b = bh >> 4, h = bh & 15;
    int t = threadIdx.x;
    int w = t >> 5, lane = t & 31;
    int g = lane >> 2, q = lane & 3;

    auto load_kv = [&](int st, int kt) {
        unsigned short* sg = sKV + st * AST;
        size_t kbase = ((size_t)bh * S_LEN + kt * 128) * HDIM;
        #pragma unroll
        for (int i = 0; i < 4; ++i) {          // K: 128 rows x 8 chunks
            int ch = t + i * 256;              // 0..1023
            int row = ch >> 3, c = ch & 7;
            cp16(sg + row * APAD + c * 8, Kh + kbase + row * 64 + c * 8);
        }
        #pragma unroll
        for (int i = 0; i < 4; ++i) {          // V^T: 64 rows x 16 chunks
            int ch = t + i * 256;              // 0..1023
            int row = ch >> 4, c = ch & 15;
            size_t vsrc = ((size_t)bh * HDIM + row) * S_LEN + kt * 128 + c * 8;
            cp16(sg + KT + row * VPAD + c * 8, Vth + vsrc);
        }
        cp_commit();
    };

    // prologue: stage Q, prefetch kv tile 0
    size_t qbase = ((size_t)bh * S_LEN + qt * 128) * HDIM;
    #pragma unroll
    for (int i = 0; i < 4; ++i) {
        int ch = t + i * 256;                  // 0..1023
        int row = ch >> 3, c = ch & 7;
        cp16(sQh + row * APAD + c * 8, Qh + qbase + row * 64 + c * 8);
    }
    cp_commit();
    load_kv(0, 0);

    // init V^T rows 64..79 in both stages (cp.async only touches rows 0..63):
    // rows 64..71 = ones over s cols 0..127 (the l-block), rows 72..79 = zero.
    for (int idx = t; idx < 16 * VPAD; idx += 256) {
        int row = idx / VPAD, col = idx % VPAD;
        unsigned short val = (row < 8 && col < 128) ? (unsigned short)0x3C00
                                                    : (unsigned short)0;
        sKV[KT + (64 + row) * VPAD + col]       = val;
        sKV[AST + KT + (64 + row) * VPAD + col] = val;
    }

    cp_wait1();
    __syncthreads();

    uint32_t qfh[4][4];
    #pragma unroll
    for (int kk = 0; kk < 4; ++kk) {
        int r = w * 16 + (lane & 15);
        int c = kk * 16 + (lane >> 4) * 8;
        ldsm4(qfh[kk], sQh + r * APAD + c);
    }

    float o[9][4];
    #pragma unroll
    for (int nt = 0; nt < 9; ++nt)
        #pragma unroll
        for (int e = 0; e < 4; ++e) o[nt][e] = 0.f;
    float mA = -1e30f, mB = -1e30f;

    int qrA = qt * 128 + w * 16 + g;
    int nk = qt + 1;

    for (int kt = 0; kt < nk; ++kt) {
        cp_wait0();
        __syncthreads();
        if (kt + 1 < nk) load_kv((kt + 1) & 1, kt + 1);

        unsigned short* sg  = sKV + (kt & 1) * AST;
        unsigned short* sK_ = sg;
        unsigned short* sV_ = sg + KT;

        // S = Q K^T  (logits in log2 units)
        float s_acc[16][4];
        #pragma unroll
        for (int nt = 0; nt < 16; ++nt)
            #pragma unroll
            for (int e = 0; e < 4; ++e) s_acc[nt][e] = 0.f;

        #pragma unroll
        for (int kk = 0; kk < 4; ++kk) {
            uint32_t bh2[16][2];
            #pragma unroll
            for (int p = 0; p < 8; ++p) {
                int r = p * 16 + ((lane >> 4) & 1) * 8 + (lane & 7);
                int c = kk * 16 + ((lane >> 3) & 1) * 8;
                uint32_t tmp[4];
                ldsm4(tmp, sK_ + r * APAD + c);
                bh2[2*p][0] = tmp[0]; bh2[2*p][1] = tmp[1];
                bh2[2*p+1][0] = tmp[2]; bh2[2*p+1][1] = tmp[3];
            }
            #pragma unroll
            for (int nt = 0; nt < 16; ++nt)
                mma_f16(s_acc[nt], qfh[kk], bh2[nt]);
        }

        // causal mask
        int kb0 = kt * 128;
        if (kb0 + 127 > qrA) {
            #pragma unroll
            for (int nt = 0; nt < 16; ++nt) {
                int colb = kb0 + nt * 8 + 2 * q;
                if (colb     > qrA)     s_acc[nt][0] = -1e30f;
                if (colb + 1 > qrA)     s_acc[nt][1] = -1e30f;
                if (colb     > qrA + 8) s_acc[nt][2] = -1e30f;
                if (colb + 1 > qrA + 8) s_acc[nt][3] = -1e30f;
            }
        }

        // row max (shuffles over the quad)
        float mxA = -1e30f, mxB = -1e30f;
        #pragma unroll
        for (int nt = 0; nt < 16; ++nt) {
            mxA = fmaxf(mxA, fmaxf(s_acc[nt][0], s_acc[nt][1]));
            mxB = fmaxf(mxB, fmaxf(s_acc[nt][2], s_acc[nt][3]));
        }
        mxA = fmaxf(mxA, __shfl_xor_sync(0xffffffffu, mxA, 1));
        mxA = fmaxf(mxA, __shfl_xor_sync(0xffffffffu, mxA, 2));
        mxB = fmaxf(mxB, __shfl_xor_sync(0xffffffffu, mxB, 1));
        mxB = fmaxf(mxB, __shfl_xor_sync(0xffffffffu, mxB, 2));
        float mnA = fmaxf(mA, mxA), mnB = fmaxf(mB, mxB);
        float corrA = exp2f(mA - mnA), corrB = exp2f(mB - mnB);
        mA = mnA;  mB = mnB;

        // P = exp2(s - m) computed directly in fp16 pairs (2 scores / MUFU)
        uint32_t pA[16], pB[16];
        #pragma unroll
        for (int nt = 0; nt < 16; ++nt) {
            pA[nt] = ex2_h2(f2h2(s_acc[nt][0] - mnA, s_acc[nt][1] - mnA));
            pB[nt] = ex2_h2(f2h2(s_acc[nt][2] - mnB, s_acc[nt][3] - mnB));
        }

        // rescale O (incl. l in o[8])
        #pragma unroll
        for (int nt = 0; nt < 9; ++nt) {
            o[nt][0] *= corrA; o[nt][1] *= corrA;
            o[nt][2] *= corrB; o[nt][3] *= corrB;
        }

        // O += P V  (rows 64..71 of V are ones -> o[8][0]=lA, o[8][2]=lB)
        #pragma unroll
        for (int kk = 0; kk < 8; ++kk) {
            int n0 = 2 * kk, n1 = 2 * kk + 1;
            uint32_t ph[4];
            ph[0] = pA[n0]; ph[1] = pB[n0];
            ph[2] = pA[n1]; ph[3] = pB[n1];
            uint32_t vh2[10][2];
            #pragma unroll
            for (int p = 0; p < 5; ++p) {
                int r = p * 16 + ((lane >> 4) & 1) * 8 + (lane & 7);
                int c = kk * 16 + ((lane >> 3) & 1) * 8;
                uint32_t tmp[4];
                ldsm4(tmp, sV_ + r * VPAD + c);
                vh2[2*p][0] = tmp[0]; vh2[2*p][1] = tmp[1];
                vh2[2*p+1][0] = tmp[2]; vh2[2*p+1][1] = tmp[3];
            }
            #pragma unroll
            for (int nt = 0; nt < 9; ++nt)
                mma_f16(o[nt], ph, vh2[nt]);
        }
    }

    float invA = 1.f / o[8][0], invB = 1.f / o[8][2];
    int rowA = qt * 128 + w * 16 + g;
    size_t baseA = ((size_t)(b * S_LEN + rowA)) * DMODEL + h * HDIM;
    size_t baseB = baseA + (size_t)8 * DMODEL;
    #pragma unroll
    for (int nt = 0; nt < 8; ++nt) {
        int c = nt * 8 + 2 * q;
        float a0 = o[nt][0] * invA, a1 = o[nt][1] * invA;
        float b0 = o[nt][2] * invB, b1 = o[nt][3] * invB;
        *(uint32_t*)(Ch + baseA + c) = f2h2(a0, a1);
        *(uint32_t*)(Ch + baseB + c) = f2h2(b0, b1);
    }
}

// ---------------------------------------------------------------------------
// Launcher
// ---------------------------------------------------------------------------
extern "C" void kernel_launch(void* const* d_in, const int* in_sizes, int n_in,
                              void* d_out, int out_size)
{
    const float* hs     = (const float*)d_in[0];
    const float* gamma  = (const float*)d_in[1];
    const float* beta   = (const float*)d_in[2];
    const float* qkv_w  = (const float*)d_in[3];
    const float* qkv_b  = (const float*)d_in[4];
    const float* proj_w = (const float*)d_in[5];
    const float* proj_b = (const float*)d_in[6];
    float* out = (float*)d_out;

    void *pqkv, *pxh, *pwqh, *pwph, *pch;
    void *pqh, *pkh, *pvh;
    cudaGetSymbolAddress(&pqkv, g_qkv);
    cudaGetSymbolAddress(&pxh,  g_xh);
    cudaGetSymbolAddress(&pwqh, g_wqh); cudaGetSymbolAddress(&pwph, g_wph);
    cudaGetSymbolAddress(&pch,  g_ch);
    cudaGetSymbolAddress(&pqh,  g_qhh);
    cudaGetSymbolAddress(&pkh,  g_khh); cudaGetSymbolAddress(&pvh,  g_vth);

    cudaFuncSetAttribute(mma_gemm_smem,
        cudaFuncAttributeMaxDynamicSharedMemorySize, GEMM_SMEM);
    cudaFuncSetAttribute(attn_mma_kernel,
        cudaFuncAttributeMaxDynamicSharedMemorySize, ATT_SMEM);

    // 1) LayerNorm -> fp16
    ln_split_kernel<<<ROWS, 256>>>(hs, gamma, beta, (unsigned short*)pxh);

    // weight conversions
    w_f16_kernel<<<(QKVD*DMODEL/4)/256, 256>>>(qkv_w,
        (unsigned short*)pwqh, QKVD*DMODEL/4);
    w_f16_kernel<<<(DMODEL*DMODEL/4)/256, 256>>>(proj_w,
        (unsigned short*)pwph, DMODEL*DMODEL/4);

    // 2) QKV GEMM (pure fp16)
    mma_gemm_smem<<<dim3(QKVD/128, ROWS/128), 128, GEMM_SMEM>>>(
        (unsigned short*)pxh, (unsigned short*)pwqh,
        qkv_b, (float*)pqkv, ROWS, QKVD, DMODEL);

    // 3) RoPE + relayout, V transpose
    rope_convert_kernel<<<(BATCH*S_LEN*NHEAD*32)/256, 256>>>((float*)pqkv,
        (unsigned short*)pqh, (unsigned short*)pkh);
    v_transpose_kernel<<<dim3(S_LEN/64, BH), 256>>>((float*)pqkv,
        (unsigned short*)pvh);

    // 4) Attention (fp16, KV tile 128, f16x2 exp2, l-via-MMA)
    attn_mma_kernel<<<dim3(S_LEN/128, BH), 256, ATT_SMEM>>>(
        (unsigned short*)pqh, (unsigned short*)pkh, (unsigned short*)pvh,
        (unsigned short*)pch);

    // 5) Output projection (pure fp16)
    mma_gemm_smem<<<dim3(DMODEL/128, ROWS/128), 128, GEMM_SMEM>>>(
        (unsigned short*)pch, (unsigned short*)pwph,
        proj_b, out, ROWS, DMODEL, DMODEL);
}

// round 14
// speedup vs baseline: 2.8372x; 1.2812x over previous
#include <cuda_runtime.h>
#include <cuda_fp16.h>
#include <math.h>
#include <stdint.h>

// Problem constants
#define BATCH   2
#define S_LEN   2048
#define DMODEL  1024
#define NHEAD   16
#define HDIM    64
#define QKVD    (3*DMODEL)     // 3072
#define ROWS    (BATCH*S_LEN)  // 4096
#define BH      (BATCH*NHEAD)  // 32

// Scratch (device globals). fp16 stored as ushort.
__device__ unsigned short g_xh[ROWS * DMODEL];             // LN output
__device__ unsigned short g_wqh[QKVD * DMODEL];            // weights
__device__ unsigned short g_wph[DMODEL * DMODEL];
__device__ unsigned short g_ch[ROWS * DMODEL];             // ctx
__device__ unsigned short g_qhh[BH * S_LEN * HDIM];        // Q (post-rope, *0.125*log2e)
__device__ unsigned short g_khh[BH * S_LEN * HDIM];        // K (post-rope)
__device__ unsigned short g_vseq[ROWS * DMODEL];           // V seq-major fp16
__device__ unsigned short g_vth[BH * HDIM * S_LEN];        // V^T

// ---------------------------------------------------------------------------
// helpers
// ---------------------------------------------------------------------------
__device__ __forceinline__ uint32_t f2h2(float a, float b) {
    __half2 t = __floats2half2_rn(a, b);
    return *reinterpret_cast<uint32_t*>(&t);
}
__device__ __forceinline__ uint32_t ex2_h2(uint32_t x) {
    uint32_t r;
    asm("ex2.approx.f16x2 %0, %1;" : "=r"(r) : "r"(x));
    return r;
}
__device__ __forceinline__ uint32_t sptr(const void* p) {
    return (uint32_t)__cvta_generic_to_shared(p);
}
__device__ __forceinline__ void cp16(void* dst, const void* src) {
    asm volatile("cp.async.cg.shared.global [%0], [%1], 16;\n"
                 :: "r"(sptr(dst)), "l"(src));
}
__device__ __forceinline__ void cp_commit() { asm volatile("cp.async.commit_group;\n"); }
__device__ __forceinline__ void cp_wait0()  { asm volatile("cp.async.wait_group 0;\n"); }
__device__ __forceinline__ void cp_wait1()  { asm volatile("cp.async.wait_group 1;\n"); }

__device__ __forceinline__ void ldsm4(uint32_t* r, const void* p) {
    asm volatile("ldmatrix.sync.aligned.m8n8.x4.shared.b16 {%0,%1,%2,%3}, [%4];\n"
                 : "=r"(r[0]), "=r"(r[1]), "=r"(r[2]), "=r"(r[3]) : "r"(sptr(p)));
}
// f16 inputs, f32 accumulate
__device__ __forceinline__ void mma_f16(float* c, const uint32_t* a, const uint32_t* b) {
    asm volatile(
        "mma.sync.aligned.m16n8k16.row.col.f32.f16.f16.f32 "
        "{%0,%1,%2,%3}, {%4,%5,%6,%7}, {%8,%9}, {%0,%1,%2,%3};\n"
        : "+f"(c[0]), "+f"(c[1]), "+f"(c[2]), "+f"(c[3])
        : "r"(a[0]), "r"(a[1]), "r"(a[2]), "r"(a[3]), "r"(b[0]), "r"(b[1]));
}

// rope angle: cos/sin of s * 10000^(-2i/64), float Cody-Waite reduction
__device__ __forceinline__ void rope_cs(float s, int i, float& c, float& sn) {
    float invf = exp2f(-0.4152410118609203f * (float)i);
    float ang = s * invf;
    float n = rintf(ang * 0.15915494309189535f);
    float ar = fmaf(n, -6.28125f, ang);
    ar = fmaf(n, -1.9353071795864769e-3f, ar);
    c  = __cosf(ar);
    sn = __sinf(ar);
}

// ---------------------------------------------------------------------------
// 1) LayerNorm -> fp16 output
// ---------------------------------------------------------------------------
__global__ void __launch_bounds__(256) ln_split_kernel(
    const float* __restrict__ x, const float* __restrict__ gamma,
    const float* __restrict__ beta, unsigned short* __restrict__ yh)
{
    __shared__ float red_s[8], red_ss[8];
    __shared__ float sh_mean, sh_inv;
    int row = blockIdx.x;
    int tid = threadIdx.x;
    const float4* xr = (const float4*)(x + (size_t)row * DMODEL);
    float4 v = xr[tid];
    float s  = v.x + v.y + v.z + v.w;
    float ss = v.x*v.x + v.y*v.y + v.z*v.z + v.w*v.w;
    #pragma unroll
    for (int off = 16; off > 0; off >>= 1) {
        s  += __shfl_down_sync(0xffffffffu, s,  off);
        ss += __shfl_down_sync(0xffffffffu, ss, off);
    }
    int wid = tid >> 5, lane = tid & 31;
    if (lane == 0) { red_s[wid] = s; red_ss[wid] = ss; }
    __syncthreads();
    if (tid == 0) {
        float S = 0.f, SS = 0.f;
        #pragma unroll
        for (int i = 0; i < 8; ++i) { S += red_s[i]; SS += red_ss[i]; }
        float mean = S * (1.f / DMODEL);
        float var  = SS * (1.f / DMODEL) - mean * mean;
        sh_mean = mean;
        sh_inv  = rsqrtf(var + 1e-5f);
    }
    __syncthreads();
    float mean = sh_mean, inv = sh_inv;
    float4 gv = ((const float4*)gamma)[tid];
    float4 bv = ((const float4*)beta)[tid];
    float o0 = (v.x - mean) * inv * gv.x + bv.x;
    float o1 = (v.y - mean) * inv * gv.y + bv.y;
    float o2 = (v.z - mean) * inv * gv.z + bv.z;
    float o3 = (v.w - mean) * inv * gv.w + bv.w;
    uint2 hv = make_uint2(f2h2(o0, o1), f2h2(o2, o3));
    *(uint2*)(yh + (size_t)row * DMODEL + tid * 4) = hv;
}

// ---------------------------------------------------------------------------
// weights: fp32 -> fp16, 4 elements/thread
// ---------------------------------------------------------------------------
__global__ void __launch_bounds__(256) w_f16_kernel(
    const float* __restrict__ x, unsigned short* __restrict__ hi, int n4)
{
    int i = blockIdx.x * 256 + threadIdx.x;
    if (i >= n4) return;
    float4 v = ((const float4*)x)[i];
    uint2 hv = make_uint2(f2h2(v.x, v.y), f2h2(v.z, v.w));
    *(uint2*)(hi + (size_t)i * 4) = hv;
}

// ---------------------------------------------------------------------------
// 2a) QKV GEMM with fused bias + RoPE + head-major fp16 output.
//     Block 128x128, BK=32, 4 warps (2x2), warp tile 64x64.
//     Warp's 64 cols = exactly one q/k/v group of one head.
// ---------------------------------------------------------------------------
#define GPAD 40
#define GTILE (128 * GPAD)            // ushorts per tile
#define GSTAGE (2 * GTILE)            // Ah,Bh
#define GEMM_SMEM (2 * GSTAGE * 2)    // bytes = 40960

__global__ void __launch_bounds__(128) qkv_gemm_rope(
    const unsigned short* __restrict__ Ahg, const unsigned short* __restrict__ Bhg,
    const float* __restrict__ bias,
    unsigned short* __restrict__ Qh, unsigned short* __restrict__ Kh,
    unsigned short* __restrict__ Vseq)
{
    extern __shared__ unsigned short smg[];
    const int K = DMODEL;
    int t = threadIdx.x;
    int wid = t >> 5, lane = t & 31;
    int wm = wid >> 1, wn = wid & 1;
    int g = lane >> 2, q = lane & 3;
    int mb = blockIdx.y * 128, nb = blockIdx.x * 128;

    float acc[4][8][4];
    #pragma unroll
    for (int mt = 0; mt < 4; ++mt)
        #pragma unroll
        for (int nt = 0; nt < 8; ++nt)
            #pragma unroll
            for (int e = 0; e < 4; ++e) acc[mt][nt][e] = 0.f;

    const int NKB = K >> 5;

    auto load_stage = [&](int st, int k0) {
        unsigned short* base = smg + st * GSTAGE;
        #pragma unroll
        for (int i = 0; i < 4; ++i) {
            int ch = t + i * 128;
            int row = ch >> 2, c = ch & 3;
            int soff = row * GPAD + c * 8;
            size_t goffA = (size_t)(mb + row) * K + k0 + c * 8;
            size_t goffB = (size_t)(nb + row) * K + k0 + c * 8;
            cp16(base + soff,         Ahg + goffA);
            cp16(base + GTILE + soff, Bhg + goffB);
        }
        cp_commit();
    };

    load_stage(0, 0);

    for (int kb = 0; kb < NKB; ++kb) {
        cp_wait0();
        __syncthreads();
        if (kb + 1 < NKB) load_stage((kb + 1) & 1, (kb + 1) << 5);

        unsigned short* base = smg + (kb & 1) * GSTAGE;
        unsigned short* sAh = base;
        unsigned short* sBh = base + GTILE;

        #pragma unroll
        for (int kk = 0; kk < 2; ++kk) {
            uint32_t ah[4][4];
            #pragma unroll
            for (int mt = 0; mt < 4; ++mt) {
                int r = wm * 64 + mt * 16 + (lane & 15);
                int c = kk * 16 + (lane >> 4) * 8;
                ldsm4(ah[mt], sAh + r * GPAD + c);
            }
            uint32_t bh2[8][2];
            #pragma unroll
            for (int p = 0; p < 4; ++p) {
                int r = wn * 64 + p * 16 + ((lane >> 4) & 1) * 8 + (lane & 7);
                int c = kk * 16 + ((lane >> 3) & 1) * 8;
                uint32_t tmp[4];
                ldsm4(tmp, sBh + r * GPAD + c);
                bh2[2*p][0] = tmp[0]; bh2[2*p][1] = tmp[1];
                bh2[2*p+1][0] = tmp[2]; bh2[2*p+1][1] = tmp[3];
            }
            #pragma unroll
            for (int mt = 0; mt < 4; ++mt)
                #pragma unroll
                for (int nt = 0; nt < 8; ++nt)
                    mma_f16(acc[mt][nt], ah[mt], bh2[nt]);
        }
    }

    // ---- fused epilogue: bias + rope + head-major fp16 stores ----
    int gid  = (nb + wn * 64) >> 6;      // 0..47
    int head = gid / 3;
    int part = gid - head * 3;           // 0=q, 1=k, 2=v
    const float* bgrp = bias + (gid << 6);
    const float QS = 0.125f * 1.4426950408889634f;

    if (part < 2) {
        float scale = (part == 0) ? QS : 1.f;
        unsigned short* dstbuf = (part == 0) ? Qh : Kh;
        #pragma unroll
        for (int mt = 0; mt < 4; ++mt) {
            #pragma unroll
            for (int half = 0; half < 2; ++half) {
                int sb = mb + wm * 64 + mt * 16 + g + half * 8;
                int srow = sb & (S_LEN - 1);
                int bb = sb >> 11;
                float sf = (float)srow;
                size_t dbase = ((size_t)(bb * NHEAD + head) * S_LEN + srow) * HDIM;
                int e0 = half * 2, e1 = half * 2 + 1;
                #pragma unroll
                for (int nt = 0; nt < 4; ++nt) {
                    int i0 = nt * 8 + 2 * q;     // < 32
                    float c0, s0, c1, s1;
                    rope_cs(sf, i0,     c0, s0);
                    rope_cs(sf, i0 + 1, c1, s1);
                    float x1a = acc[mt][nt][e0]     + bgrp[i0];
                    float x1b = acc[mt][nt][e1]     + bgrp[i0 + 1];
                    float x2a = acc[mt][nt + 4][e0] + bgrp[i0 + 32];
                    float x2b = acc[mt][nt + 4][e1] + bgrp[i0 + 33];
                    float o1a = (x1a * c0 - x2a * s0) * scale;
                    float o1b = (x1b * c1 - x2b * s1) * scale;
                    float o2a = (x2a * c0 + x1a * s0) * scale;
                    float o2b = (x2b * c1 + x1b * s1) * scale;
                    *(uint32_t*)(dstbuf + dbase + i0)      = f2h2(o1a, o1b);
                    *(uint32_t*)(dstbuf + dbase + i0 + 32) = f2h2(o2a, o2b);
                }
            }
        }
    } else {
        #pragma unroll
        for (int mt = 0; mt < 4; ++mt) {
            #pragma unroll
            for (int half = 0; half < 2; ++half) {
                int sb = mb + wm * 64 + mt * 16 + g + half * 8;
                size_t dbase = (size_t)sb * DMODEL + head * HDIM;
                int e0 = half * 2, e1 = half * 2 + 1;
                #pragma unroll
                for (int nt = 0; nt < 8; ++nt) {
                    int d0 = nt * 8 + 2 * q;
                    float va = acc[mt][nt][e0] + bgrp[d0];
                    float vb = acc[mt][nt][e1] + bgrp[d0 + 1];
                    *(uint32_t*)(Vseq + dbase + d0) = f2h2(va, vb);
                }
            }
        }
    }
}

// ---------------------------------------------------------------------------
// 2b) Generic pure-fp16 GEMM (fp32 out + bias) for the projection.
// ---------------------------------------------------------------------------
__global__ void __launch_bounds__(128) mma_gemm_smem(
    const unsigned short* __restrict__ Ahg, const unsigned short* __restrict__ Bhg,
    const float* __restrict__ bias, float* __restrict__ C,
    int M, int N, int K)
{
    extern __shared__ unsigned short smg[];
    int t = threadIdx.x;
    int wid = t >> 5, lane = t & 31;
    int wm = wid >> 1, wn = wid & 1;
    int g = lane >> 2, q = lane & 3;
    int mb = blockIdx.y * 128, nb = blockIdx.x * 128;

    float acc[4][8][4];
    #pragma unroll
    for (int mt = 0; mt < 4; ++mt)
        #pragma unroll
        for (int nt = 0; nt < 8; ++nt)
            #pragma unroll
            for (int e = 0; e < 4; ++e) acc[mt][nt][e] = 0.f;

    const int NKB = K >> 5;

    auto load_stage = [&](int st, int k0) {
        unsigned short* base = smg + st * GSTAGE;
        #pragma unroll
        for (int i = 0; i < 4; ++i) {
            int ch = t + i * 128;
            int row = ch >> 2, c = ch & 3;
            int soff = row * GPAD + c * 8;
            size_t goffA = (size_t)(mb + row) * K + k0 + c * 8;
            size_t goffB = (size_t)(nb + row) * K + k0 + c * 8;
            cp16(base + soff,         Ahg + goffA);
            cp16(base + GTILE + soff, Bhg + goffB);
        }
        cp_commit();
    };

    load_stage(0, 0);

    for (int kb = 0; kb < NKB; ++kb) {
        cp_wait0();
        __syncthreads();
        if (kb + 1 < NKB) load_stage((kb + 1) & 1, (kb + 1) << 5);

        unsigned short* base = smg + (kb & 1) * GSTAGE;
        unsigned short* sAh = base;
        unsigned short* sBh = base + GTILE;

        #pragma unroll
        for (int kk = 0; kk < 2; ++kk) {
            uint32_t ah[4][4];
            #pragma unroll
            for (int mt = 0; mt < 4; ++mt) {
                int r = wm * 64 + mt * 16 + (lane & 15);
                int c = kk * 16 + (lane >> 4) * 8;
                ldsm4(ah[mt], sAh + r * GPAD + c);
            }
            uint32_t bh2[8][2];
            #pragma unroll
            for (int p = 0; p < 4; ++p) {
                int r = wn * 64 + p * 16 + ((lane >> 4) & 1) * 8 + (lane & 7);
                int c = kk * 16 + ((lane >> 3) & 1) * 8;
                uint32_t tmp[4];
                ldsm4(tmp, sBh + r * GPAD + c);
                bh2[2*p][0] = tmp[0]; bh2[2*p][1] = tmp[1];
                bh2[2*p+1][0] = tmp[2]; bh2[2*p+1][1] = tmp[3];
            }
            #pragma unroll
            for (int mt = 0; mt < 4; ++mt)
                #pragma unroll
                for (int nt = 0; nt < 8; ++nt)
                    mma_f16(acc[mt][nt], ah[mt], bh2[nt]);
        }
    }

    #pragma unroll
    for (int mt = 0; mt < 4; ++mt) {
        #pragma unroll
        for (int nt = 0; nt < 8; ++nt) {
            int r = mb + wm * 64 + mt * 16 + g;
            int c = nb + wn * 64 + nt * 8 + q * 2;
            float b0 = bias[c], b1 = bias[c + 1];
            float2 v0; v0.x = acc[mt][nt][0] + b0; v0.y = acc[mt][nt][1] + b1;
            float2 v1; v1.x = acc[mt][nt][2] + b0; v1.y = acc[mt][nt][3] + b1;
            *(float2*)(C + (size_t)r * N + c)       = v0;
            *(float2*)(C + (size_t)(r + 8) * N + c) = v1;
        }
    }
}

// ---------------------------------------------------------------------------
// 3) V transpose (fp16 in, fp16 out): Vt[bh][d][s].
// ---------------------------------------------------------------------------
__global__ void __launch_bounds__(256) v_transpose_kernel(
    const unsigned short* __restrict__ vseq, unsigned short* __restrict__ Vth)
{
    __shared__ unsigned short tile[64][66];
    int st = blockIdx.x, bh = blockIdx.y;
    int b = bh >> 4, h = bh & 15;
    int t = threadIdx.x;
    #pragma unroll
    for (int it = 0; it < 4; ++it) {
        int id = t + it * 256;            // 0..1023
        int sl = id >> 4, f4 = id & 15;
        size_t src = (size_t)(b * S_LEN + st * 64 + sl) * DMODEL + h * HDIM + f4 * 4;
        uint2 v = *(const uint2*)(vseq + src);
        *(uint32_t*)&tile[sl][f4 * 4]     = v.x;
        *(uint32_t*)&tile[sl][f4 * 4 + 2] = v.y;
    }
    __syncthreads();
    #pragma unroll
    for (int it = 0; it < 16; ++it) {
        int d  = it * 4 + (t >> 6);
        int sl = t & 63;
        size_t dst = ((size_t)bh * HDIM + d) * S_LEN + st * 64 + sl;
        Vth[dst] = tile[sl][d];
    }
}

// ---------------------------------------------------------------------------
// 4) fp16 flash attention, KV tile 128, f16x2 exp2, l-via-MMA ones rows.
//    Pipelined: S(t+1) issued BEFORE PV(t) so PV fills the tensor pipe
//    while softmax(t+1) dependencies complete.
// ---------------------------------------------------------------------------
#define APAD 72            // K/Q row pad
#define VPAD 136           // V^T row pad
#define VROWS 80           // 64 d-rows + ones rows 64..71 + zero 72..79
#define AQT (128 * APAD)
#define KT  (128 * APAD)
#define VT  (VROWS * VPAD)
#define AST (KT + VT)
#define ATT_SMEM ((AQT + 2 * AST) * 2)

__global__ void __launch_bounds__(256) attn_mma_kernel(
    const unsigned short* __restrict__ Qh,
    const unsigned short* __restrict__ Kh, const unsigned short* __restrict__ Vth,
    unsigned short* __restrict__ Ch)
{
    extern __shared__ unsigned short sma[];
    unsigned short* sQh = sma;
    unsigned short* sKV = sma + AQT;

    int qt = gridDim.x - 1 - blockIdx.x;
    int bh = blockIdx.y;
    int b = bh >> 4, h = bh & 15;
    int t = threadIdx.x;
    int w = t >> 5, lane = t & 31;
    int g = lane >> 2, q = lane & 3;

    auto load_kv = [&](int st, int kt) {
        unsigned short* sg = sKV + st * AST;
        size_t kbase = ((size_t)bh * S_LEN + kt * 128) * HDIM;
        #pragma unroll
        for (int i = 0; i < 4; ++i) {
            int ch = t + i * 256;
            int row = ch >> 3, c = ch & 7;
            cp16(sg + row * APAD + c * 8, Kh + kbase + row * 64 + c * 8);
        }
        #pragma unroll
        for (int i = 0; i < 4; ++i) {
            int ch = t + i * 256;
            int row = ch >> 4, c = ch & 15;
            size_t vsrc = ((size_t)bh * HDIM + row) * S_LEN + kt * 128 + c * 8;
            cp16(sg + KT + row * VPAD + c * 8, Vth + vsrc);
        }
        cp_commit();
    };

    int nk = qt + 1;

    // prologue: Q, kv0, (kv1)
    size_t qbase = ((size_t)bh * S_LEN + qt * 128) * HDIM;
    #pragma unroll
    for (int i = 0; i < 4; ++i) {
        int ch = t + i * 256;
        int row = ch >> 3, c = ch & 7;
        cp16(sQh + row * APAD + c * 8, Qh + qbase + row * 64 + c * 8);
    }
    cp_commit();
    load_kv(0, 0);
    if (nk > 1) load_kv(1, 1);

    // init V^T rows 64..79 in both stages (cp.async never touches them)
    for (int idx = t; idx < 16 * VPAD; idx += 256) {
        int row = idx / VPAD, col = idx % VPAD;
        unsigned short val = (row < 8 && col < 128) ? (unsigned short)0x3C00
                                                    : (unsigned short)0;
        sKV[KT + (64 + row) * VPAD + col]       = val;
        sKV[AST + KT + (64 + row) * VPAD + col] = val;
    }

    if (nk > 1) cp_wait1(); else cp_wait0();
    __syncthreads();

    uint32_t qfh[4][4];
    #pragma unroll
    for (int kk = 0; kk < 4; ++kk) {
        int r = w * 16 + (lane & 15);
        int c = kk * 16 + (lane >> 4) * 8;
        ldsm4(qfh[kk], sQh + r * APAD + c);
    }

    float o[9][4];
    #pragma unroll
    for (int nt = 0; nt < 9; ++nt)
        #pragma unroll
        for (int e = 0; e < 4; ++e) o[nt][e] = 0.f;
    float mA = -1e30f, mB = -1e30f;

    int qrA = qt * 128 + w * 16 + g;
    float s_acc[16][4];
    uint32_t pA[16], pB[16];

    auto s_phase = [&](int st) {
        unsigned short* sK_ = sKV + st * AST;
        #pragma unroll
        for (int nt = 0; nt < 16; ++nt)
            #pragma unroll
            for (int e = 0; e < 4; ++e) s_acc[nt][e] = 0.f;
        #pragma unroll
        for (int kk = 0; kk < 4; ++kk) {
            uint32_t bh2[16][2];
            #pragma unroll
            for (int p = 0; p < 8; ++p) {
                int r = p * 16 + ((lane >> 4) & 1) * 8 + (lane & 7);
                int c = kk * 16 + ((lane >> 3) & 1) * 8;
                uint32_t tmp[4];
                ldsm4(tmp, sK_ + r * APAD + c);
                bh2[2*p][0] = tmp[0]; bh2[2*p][1] = tmp[1];
                bh2[2*p+1][0] = tmp[2]; bh2[2*p+1][1] = tmp[3];
            }
            #pragma unroll
            for (int nt = 0; nt < 16; ++nt)
                mma_f16(s_acc[nt], qfh[kk], bh2[nt]);
        }
    };

    auto pv_phase = [&](int st) {
        unsigned short* sV_ = sKV + st * AST + KT;
        #pragma unroll
        for (int kk = 0; kk < 8; ++kk) {
            int n0 = 2 * kk, n1 = 2 * kk + 1;
            uint32_t ph[4];
            ph[0] = pA[n0]; ph[1] = pB[n0];
            ph[2] = pA[n1]; ph[3] = pB[n1];
            uint32_t vh2[10][2];
            #pragma unroll
            for (int p = 0; p < 5; ++p) {
                int r = p * 16 + ((lane >> 4) & 1) * 8 + (lane & 7);
                int c = kk * 16 + ((lane >> 3) & 1) * 8;
                uint32_t tmp[4];
                ldsm4(tmp, sV_ + r * VPAD + c);
                vh2[2*p][0] = tmp[0]; vh2[2*p][1] = tmp[1];
                vh2[2*p+1][0] = tmp[2]; vh2[2*p+1][1] = tmp[3];
            }
            #pragma unroll
            for (int nt = 0; nt < 9; ++nt)
                mma_f16(o[nt], ph, vh2[nt]);
        }
    };

    s_phase(0);

    for (int kt = 0; kt < nk; ++kt) {
        // ---- softmax on tile kt (s_acc holds S(kt)) ----
        int kb0 = kt * 128;
        if (kb0 + 127 > qrA) {
            #pragma unroll
            for (int nt = 0; nt < 16; ++nt) {
                int colb = kb0 + nt * 8 + 2 * q;
                if (colb     > qrA)     s_acc[nt][0] = -1e30f;
                if (colb + 1 > qrA)     s_acc[nt][1] = -1e30f;
                if (colb     > qrA + 8) s_acc[nt][2] = -1e30f;
                if (colb + 1 > qrA + 8) s_acc[nt][3] = -1e30f;
            }
        }
        float mxA = -1e30f, mxB = -1e30f;
        #pragma unroll
        for (int nt = 0; nt < 16; ++nt) {
            mxA = fmaxf(mxA, fmaxf(s_acc[nt][0], s_acc[nt][1]));
            mxB = fmaxf(mxB, fmaxf(s_acc[nt][2], s_acc[nt][3]));
        }
        mxA = fmaxf(mxA, __shfl_xor_sync(0xffffffffu, mxA, 1));
        mxA = fmaxf(mxA, __shfl_xor_sync(0xffffffffu, mxA, 2));
        mxB = fmaxf(mxB, __shfl_xor_sync(0xffffffffu, mxB, 1));
        mxB = fmaxf(mxB, __shfl_xor_sync(0xffffffffu, mxB, 2));
        float mnA = fmaxf(mA, mxA), mnB = fmaxf(mB, mxB);
        float corrA = exp2f(mA - mnA), corrB = exp2f(mB - mnB);
        mA = mnA;  mB = mnB;
        #pragma unroll
        for (int nt = 0; nt < 16; ++nt) {
            pA[nt] = ex2_h2(f2h2(s_acc[nt][0] - mnA, s_acc[nt][1] - mnA));
            pB[nt] = ex2_h2(f2h2(s_acc[nt][2] - mnB, s_acc[nt][3] - mnB));
        }
        #pragma unroll
        for (int nt = 0; nt < 9; ++nt) {
            o[nt][0] *= corrA; o[nt][1] *= corrA;
            o[nt][2] *= corrB; o[nt][3] *= corrB;
        }

        // ---- S(kt+1) before PV(kt): PV keeps tensor pipe fed while the
        //      next softmax's dependencies (S(kt+1)) complete. ----
        if (kt + 1 < nk) {
            cp_wait0();        // load(kt+1) done (only outstanding group)
            __syncthreads();   // publish stage (kt+1)&1
            s_phase((kt + 1) & 1);
        }

        pv_phase(kt & 1);

        __syncthreads();       // all warps done reading stage kt&1
        if (kt + 2 < nk) load_kv(kt & 1, kt + 2);
    }

    float invA = 1.f / o[8][0], invB = 1.f / o[8][2];
    int rowA = qt * 128 + w * 16 + g;
    size_t baseA = ((size_t)(b * S_LEN + rowA)) * DMODEL + h * HDIM;
    size_t baseB = baseA + (size_t)8 * DMODEL;
    #pragma unroll
    for (int nt = 0; nt < 8; ++nt) {
        int c = nt * 8 + 2 * q;
        float a0 = o[nt][0] * invA, a1 = o[nt][1] * invA;
        float b0 = o[nt][2] * invB, b1 = o[nt][3] * invB;
        *(uint32_t*)(Ch + baseA + c) = f2h2(a0, a1);
        *(uint32_t*)(Ch + baseB + c) = f2h2(b0, b1);
    }
}

// ---------------------------------------------------------------------------
// Launcher
// ---------------------------------------------------------------------------
extern "C" void kernel_launch(void* const* d_in, const int* in_sizes, int n_in,
                              void* d_out, int out_size)
{
    const float* hs     = (const float*)d_in[0];
    const float* gamma  = (const float*)d_in[1];
    const float* beta   = (const float*)d_in[2];
    const float* qkv_w  = (const float*)d_in[3];
    const float* qkv_b  = (const float*)d_in[4];
    const float* proj_w = (const float*)d_in[5];
    const float* proj_b = (const float*)d_in[6];
    float* out = (float*)d_out;

    void *pxh, *pwqh, *pwph, *pch, *pqh, *pkh, *pvs, *pvh;
    cudaGetSymbolAddress(&pxh,  g_xh);
    cudaGetSymbolAddress(&pwqh, g_wqh); cudaGetSymbolAddress(&pwph, g_wph);
    cudaGetSymbolAddress(&pch,  g_ch);
    cudaGetSymbolAddress(&pqh,  g_qhh); cudaGetSymbolAddress(&pkh,  g_khh);
    cudaGetSymbolAddress(&pvs,  g_vseq); cudaGetSymbolAddress(&pvh,  g_vth);

    cudaFuncSetAttribute(qkv_gemm_rope,
        cudaFuncAttributeMaxDynamicSharedMemorySize, GEMM_SMEM);
    cudaFuncSetAttribute(mma_gemm_smem,
        cudaFuncAttributeMaxDynamicSharedMemorySize, GEMM_SMEM);
    cudaFuncSetAttribute(attn_mma_kernel,
        cudaFuncAttributeMaxDynamicSharedMemorySize, ATT_SMEM);

    // 1) LayerNorm -> fp16
    ln_split_kernel<<<ROWS, 256>>>(hs, gamma, beta, (unsigned short*)pxh);

    // weight conversions
    w_f16_kernel<<<(QKVD*DMODEL/4)/256, 256>>>(qkv_w,
        (unsigned short*)pwqh, QKVD*DMODEL/4);
    w_f16_kernel<<<(DMODEL*DMODEL/4)/256, 256>>>(proj_w,
        (unsigned short*)pwph, DMODEL*DMODEL/4);

    // 2) QKV GEMM with fused bias+rope+relayout (fp16 out)
    qkv_gemm_rope<<<dim3(QKVD/128, ROWS/128), 128, GEMM_SMEM>>>(
        (unsigned short*)pxh, (unsigned short*)pwqh, qkv_b,
        (unsigned short*)pqh, (unsigned short*)pkh, (unsigned short*)pvs);

    // 3) V transpose (fp16 -> fp16)
    v_transpose_kernel<<<dim3(S_LEN/64, BH), 256>>>(
        (unsigned short*)pvs, (unsigned short*)pvh);

    // 4) Attention (pipelined S/PV overlap)
    attn_mma_kernel<<<dim3(S_LEN/128, BH), 256, ATT_SMEM>>>(
        (unsigned short*)pqh, (unsigned short*)pkh, (unsigned short*)pvh,
        (unsigned short*)pch);

    // 5) Output projection (fp32 out)
    mma_gemm_smem<<<dim3(DMODEL/128, ROWS/128), 128, GEMM_SMEM>>>(
        (unsigned short*)pch, (unsigned short*)pwph,
        proj_b, out, ROWS, DMODEL, DMODEL);
}